// round 1
// baseline (speedup 1.0000x reference)
#include <cuda_runtime.h>
#include <cstdint>

#define NNODES 100000
#define NEDGES 1600000
#define HF 64

// ---------------- static device scratch (no allocation allowed) ----------------
__device__ float g_h1[NNODES * HF];
__device__ float g_f0[NNODES * HF];
__device__ float g_f1[NNODES * HF];
__device__ float g_f2[NNODES * HF];
__device__ int   g_src[NEDGES];
__device__ int   g_dst[NEDGES];
__device__ int   g_csrc[NEDGES];
__device__ int   g_deg[NNODES];
__device__ int   g_rowptr[NNODES + 1];
__device__ int   g_cursor[NNODES];
__device__ float g_dinv[NNODES];
__device__ float g_wfold[3 * 64 * 64];
__device__ int   g_flag;   // 0 = edge_index is int64, 1 = int32

// ---------------- init ----------------
__global__ void k_init() {
    int i = blockIdx.x * blockDim.x + threadIdx.x;
    if (i < NNODES) g_deg[i] = 0;
    if (i == 0) g_flag = 0;
}

// detect dtype of edge_index: if int64, the high 32-bit word of every entry is 0
__global__ void k_detect(const int* __restrict__ e32) {
    int i = blockIdx.x * blockDim.x + threadIdx.x;
    int stride = gridDim.x * blockDim.x;
    for (int e = i; e < NEDGES; e += stride) {
        if (e32[2 * e + 1] != 0) { g_flag = 1; break; }
    }
}

// convert edges to int32 src/dst and count in-degree
__global__ void k_convert_degree(const void* __restrict__ eptr) {
    int e = blockIdx.x * blockDim.x + threadIdx.x;
    if (e >= NEDGES) return;
    int s, d;
    if (g_flag == 0) {
        const long long* p = (const long long*)eptr;
        s = (int)p[e];
        d = (int)p[NEDGES + e];
    } else {
        const int* p = (const int*)eptr;
        s = p[e];
        d = p[NEDGES + e];
    }
    g_src[e] = s;
    g_dst[e] = d;
    atomicAdd(&g_deg[d], 1);
}

// single-block exclusive scan of degrees -> rowptr, cursor, dinv
__global__ void k_scan() {
    __shared__ int sums[1024];
    int tid = threadIdx.x;
    const int CH = (NNODES + 1023) / 1024;   // 98
    int base = tid * CH;
    int s = 0;
    for (int j = 0; j < CH; j++) {
        int idx = base + j;
        if (idx < NNODES) s += g_deg[idx];
    }
    sums[tid] = s;
    __syncthreads();
    for (int off = 1; off < 1024; off <<= 1) {
        int v = (tid >= off) ? sums[tid - off] : 0;
        __syncthreads();
        sums[tid] += v;
        __syncthreads();
    }
    int run = (tid == 0) ? 0 : sums[tid - 1];
    for (int j = 0; j < CH; j++) {
        int idx = base + j;
        if (idx < NNODES) {
            g_rowptr[idx] = run;
            g_cursor[idx] = run;
            int d = g_deg[idx];
            g_dinv[idx] = rsqrtf((float)(d > 0 ? d : 1));
            run += d;
        }
    }
    if (tid == 0) g_rowptr[NNODES] = sums[1023];
}

// scatter edges into CSR buckets (sorted by dst)
__global__ void k_fill() {
    int e = blockIdx.x * blockDim.x + threadIdx.x;
    if (e >= NEDGES) return;
    int d = g_dst[e];
    int pos = atomicAdd(&g_cursor[d], 1);
    g_csrc[pos] = g_src[e];
}

// fold thetas into Wm1: wfold_k = sum_t theta_t[k] * Wm1[t*64 : (t+1)*64, :]
// THETAS (D=2): t0=[3,-3,0.75], t1=[0,3,-1.5], t2=[0,0,0.75]
__global__ void k_fold(const float* __restrict__ Wm1) {
    int idx = blockIdx.x * blockDim.x + threadIdx.x;
    if (idx >= 3 * 64 * 64) return;
    int k = idx >> 12;
    int ij = idx & 4095;
    float c0, c1, c2;
    if (k == 0)      { c0 = 3.0f;  c1 = 0.0f;  c2 = 0.0f;  }
    else if (k == 1) { c0 = -3.0f; c1 = 3.0f;  c2 = 0.0f;  }
    else             { c0 = 0.75f; c1 = -1.5f; c2 = 0.75f; }
    g_wfold[idx] = c0 * Wm1[ij] + c1 * Wm1[4096 + ij] + c2 * Wm1[2 * 4096 + ij];
}

// ---------------- GEMM: C[M x 64] = act( sum_seg A_seg[M x 64] @ W_seg[64 x 64] + b ) ----------------
// Optionally fused final head: out[M x 2] = relu(...) @ Wm2[64 x 2] + bm2
template <int NSEG, bool RELU, bool FUSE_FINAL>
__global__ void __launch_bounds__(256) k_gemm(
    const float* __restrict__ A0, const float* __restrict__ A1, const float* __restrict__ A2,
    int lda,
    const float* __restrict__ W, const float* __restrict__ bias,
    float* __restrict__ C,
    const float* __restrict__ Wm2, const float* __restrict__ bm2,
    float* __restrict__ out)
{
    constexpr int KS = 64, PAD = 4, RPB = 16, R = 4;
    constexpr int LD = KS + PAD;                 // 68 (odd/even mix keeps LDS.128 phases conflict-free)
    __shared__ float Ws[64 * LD];                // transposed: Ws[col][k]
    __shared__ float As[RPB * LD];
    __shared__ float Zs[FUSE_FINAL ? RPB * LD : 1];

    int tid = threadIdx.x;
    int col = tid & 63;
    int ty = tid >> 6;                           // 0..3
    int row0 = blockIdx.x * RPB;

    float acc[R] = {0.f, 0.f, 0.f, 0.f};
    const float* Aseg[3] = {A0, A1, A2};

#pragma unroll
    for (int sg = 0; sg < NSEG; sg++) {
        // stage W chunk transposed
        const float* Wc = W + sg * KS * 64;
        for (int i = tid; i < KS * 64; i += 256) {
            int k = i >> 6, c = i & 63;
            Ws[c * LD + k] = Wc[i];
        }
        // stage A tile (one float4 per thread: RPB*KS/4 == 256)
        {
            int r = tid >> 4;
            int kq = tid & 15;
            const float* Ab = Aseg[sg];
            float4 v = *(const float4*)&Ab[(size_t)(row0 + r) * lda + kq * 4];
            *(float4*)&As[r * LD + kq * 4] = v;
        }
        __syncthreads();
#pragma unroll
        for (int k = 0; k < KS; k += 4) {
            float4 w = *(const float4*)&Ws[col * LD + k];
#pragma unroll
            for (int r = 0; r < R; r++) {
                float4 a = *(const float4*)&As[(ty * R + r) * LD + k];  // broadcast
                acc[r] = fmaf(a.x, w.x, acc[r]);
                acc[r] = fmaf(a.y, w.y, acc[r]);
                acc[r] = fmaf(a.z, w.z, acc[r]);
                acc[r] = fmaf(a.w, w.w, acc[r]);
            }
        }
        __syncthreads();
    }

    float bv = __ldg(&bias[col]);
    if (!FUSE_FINAL) {
#pragma unroll
        for (int r = 0; r < R; r++) {
            int row = row0 + ty * R + r;
            float v = acc[r] + bv;
            if (RELU) v = fmaxf(v, 0.f);
            C[(size_t)row * 64 + col] = v;
        }
    } else {
#pragma unroll
        for (int r = 0; r < R; r++) {
            float v = fmaxf(acc[r] + bv, 0.f);
            Zs[(ty * R + r) * LD + col] = v;
        }
        __syncthreads();
        if (tid < RPB * 2) {
            int r = tid >> 1, c2 = tid & 1;
            float sacc = __ldg(&bm2[c2]);
#pragma unroll
            for (int c = 0; c < 64; c++)
                sacc = fmaf(Zs[r * LD + c], __ldg(&Wm2[c * 2 + c2]), sacc);
            out[(size_t)(row0 + r) * 2 + c2] = sacc;
        }
    }
}

// ---------------- propagation: fout[n] = fin[n] - dinv[n] * sum_{s in in(n)} fin[s]*dinv[s] ----------------
__global__ void __launch_bounds__(256) k_prop(const float* __restrict__ fin,
                                              float* __restrict__ fout)
{
    int n = (blockIdx.x * blockDim.x + threadIdx.x) >> 5;  // grid sized exactly: no partial warps
    int lane = threadIdx.x & 31;
    int start = g_rowptr[n];
    int end = g_rowptr[n + 1];

    float ax = 0.f, ay = 0.f;
    for (int i = start; i < end; i += 32) {
        int cnt = min(32, end - i);
        int s = 0;
        if (lane < cnt) s = g_csrc[i + lane];
        int j = 0;
        for (; j + 4 <= cnt; j += 4) {
            int s0 = __shfl_sync(0xffffffffu, s, j);
            int s1 = __shfl_sync(0xffffffffu, s, j + 1);
            int s2 = __shfl_sync(0xffffffffu, s, j + 2);
            int s3 = __shfl_sync(0xffffffffu, s, j + 3);
            float d0 = __ldg(&g_dinv[s0]);
            float d1 = __ldg(&g_dinv[s1]);
            float d2 = __ldg(&g_dinv[s2]);
            float d3 = __ldg(&g_dinv[s3]);
            float2 v0 = *(const float2*)&fin[(size_t)s0 * 64 + lane * 2];
            float2 v1 = *(const float2*)&fin[(size_t)s1 * 64 + lane * 2];
            float2 v2 = *(const float2*)&fin[(size_t)s2 * 64 + lane * 2];
            float2 v3 = *(const float2*)&fin[(size_t)s3 * 64 + lane * 2];
            ax += v0.x * d0 + v1.x * d1 + v2.x * d2 + v3.x * d3;
            ay += v0.y * d0 + v1.y * d1 + v2.y * d2 + v3.y * d3;
        }
        for (; j < cnt; j++) {
            int sj = __shfl_sync(0xffffffffu, s, j);
            float dj = __ldg(&g_dinv[sj]);
            float2 v = *(const float2*)&fin[(size_t)sj * 64 + lane * 2];
            ax += v.x * dj;
            ay += v.y * dj;
        }
    }
    float dn = g_dinv[n];
    float2 cur = *(const float2*)&fin[(size_t)n * 64 + lane * 2];
    float2 o = make_float2(cur.x - ax * dn, cur.y - ay * dn);
    *(float2*)&fout[(size_t)n * 64 + lane * 2] = o;
}

// ---------------- launch ----------------
extern "C" void kernel_launch(void* const* d_in, const int* in_sizes, int n_in,
                              void* d_out, int out_size)
{
    const float* x   = (const float*)d_in[0];
    const void*  ei  = d_in[1];
    const float* W1  = (const float*)d_in[2];
    const float* b1  = (const float*)d_in[3];
    const float* W2  = (const float*)d_in[4];
    const float* b2  = (const float*)d_in[5];
    const float* Wm1 = (const float*)d_in[6];
    const float* bm1 = (const float*)d_in[7];
    const float* Wm2 = (const float*)d_in[8];
    const float* bm2 = (const float*)d_in[9];
    float* out = (float*)d_out;

    float *ph1, *pf0, *pf1, *pf2, *pwf;
    cudaGetSymbolAddress((void**)&ph1, g_h1);
    cudaGetSymbolAddress((void**)&pf0, g_f0);
    cudaGetSymbolAddress((void**)&pf1, g_f1);
    cudaGetSymbolAddress((void**)&pf2, g_f2);
    cudaGetSymbolAddress((void**)&pwf, g_wfold);

    // graph prep
    k_init<<<(NNODES + 255) / 256, 256>>>();
    k_detect<<<256, 256>>>((const int*)ei);
    k_convert_degree<<<NEDGES / 256, 256>>>(ei);
    k_scan<<<1, 1024>>>();
    k_fill<<<NEDGES / 256, 256>>>();
    k_fold<<<(3 * 64 * 64 + 255) / 256, 256>>>(Wm1);

    // MLP: h1 = relu(x @ W1 + b1)  (K=128 -> two 64-K segments)
    k_gemm<2, true, false><<<NNODES / 16, 256>>>(x, x + 64, nullptr, 128, W1, b1,
                                                 ph1, nullptr, nullptr, nullptr);
    // f0 = relu(h1 @ W2 + b2)
    k_gemm<1, true, false><<<NNODES / 16, 256>>>(ph1, nullptr, nullptr, 64, W2, b2,
                                                 pf0, nullptr, nullptr, nullptr);
    // propagation (shared across all thetas): f1 = P f0, f2 = P f1
    k_prop<<<(NNODES * 32) / 256, 256>>>(pf0, pf1);
    k_prop<<<(NNODES * 32) / 256, 256>>>(pf1, pf2);

    // head: out = relu(f0@Wf0 + f1@Wf1 + f2@Wf2 + bm1) @ Wm2 + bm2 (fused)
    k_gemm<3, true, true><<<NNODES / 16, 256>>>(pf0, pf1, pf2, 64, pwf, bm1,
                                                nullptr, Wm2, bm2, out);
}

// round 2
// speedup vs baseline: 1.7417x; 1.7417x over previous
#include <cuda_runtime.h>
#include <cstdint>

#define NNODES 100000
#define NEDGES 1600000
#define HF 64
#define SCAN_B 256
#define NBLK ((NNODES + SCAN_B - 1) / SCAN_B)   // 391

// ---------------- static device scratch ----------------
__device__ float g_h1[NNODES * HF];
__device__ float g_f0[NNODES * HF];
__device__ float g_f0s[NNODES * HF];
__device__ float g_f1[NNODES * HF];
__device__ float g_f1s[NNODES * HF];
__device__ float g_f2[NNODES * HF];
__device__ int   g_src[NEDGES];
__device__ int   g_dst[NEDGES];
__device__ int   g_csrc[NEDGES];
__device__ int   g_deg[NNODES];
__device__ int   g_rowptr[NNODES + 1];
__device__ int   g_cursor[NNODES];
__device__ float g_dinv[NNODES];
__device__ int   g_bsum[NBLK];
__device__ float g_wfold[3 * 64 * 64];
__device__ int   g_flag;   // 0 = edge_index is int64, 1 = int32

// ---------------- init ----------------
__global__ void k_init() {
    int i = blockIdx.x * blockDim.x + threadIdx.x;
    if (i < NNODES) g_deg[i] = 0;
    if (i == 0) g_flag = 0;
}

// detect dtype of edge_index: if int64, the high 32-bit word of every entry is 0
__global__ void k_detect(const int* __restrict__ e32) {
    int i = blockIdx.x * blockDim.x + threadIdx.x;
    int stride = gridDim.x * blockDim.x;
    for (int e = i; e < NEDGES; e += stride) {
        if (e32[2 * e + 1] != 0) { g_flag = 1; break; }
    }
}

// convert edges to int32 src/dst and count in-degree
__global__ void k_convert_degree(const void* __restrict__ eptr) {
    int e = blockIdx.x * blockDim.x + threadIdx.x;
    if (e >= NEDGES) return;
    int s, d;
    if (g_flag == 0) {
        const long long* p = (const long long*)eptr;
        s = (int)p[e];
        d = (int)p[NEDGES + e];
    } else {
        const int* p = (const int*)eptr;
        s = p[e];
        d = p[NEDGES + e];
    }
    g_src[e] = s;
    g_dst[e] = d;
    atomicAdd(&g_deg[d], 1);
}

// ---------------- parallel 3-phase scan ----------------
__global__ void k_blocksum() {
    __shared__ int sh[SCAN_B];
    int i = blockIdx.x * SCAN_B + threadIdx.x;
    sh[threadIdx.x] = (i < NNODES) ? g_deg[i] : 0;
    __syncthreads();
    for (int off = SCAN_B / 2; off > 0; off >>= 1) {
        if (threadIdx.x < off) sh[threadIdx.x] += sh[threadIdx.x + off];
        __syncthreads();
    }
    if (threadIdx.x == 0) g_bsum[blockIdx.x] = sh[0];
}

// inclusive scan of the 391 block sums (single tiny block)
__global__ void k_scan_bsums() {
    __shared__ int sh[512];
    int t = threadIdx.x;
    sh[t] = (t < NBLK) ? g_bsum[t] : 0;
    __syncthreads();
    for (int off = 1; off < 512; off <<= 1) {
        int v = (t >= off) ? sh[t - off] : 0;
        __syncthreads();
        sh[t] += v;
        __syncthreads();
    }
    if (t < NBLK) g_bsum[t] = sh[t];   // inclusive
}

__global__ void k_rowptr() {
    __shared__ int sh[SCAN_B];
    int b = blockIdx.x;
    int i = b * SCAN_B + threadIdx.x;
    int d = (i < NNODES) ? g_deg[i] : 0;
    sh[threadIdx.x] = d;
    __syncthreads();
    for (int off = 1; off < SCAN_B; off <<= 1) {
        int v = (threadIdx.x >= off) ? sh[threadIdx.x - off] : 0;
        __syncthreads();
        sh[threadIdx.x] += v;
        __syncthreads();
    }
    int incl = sh[threadIdx.x];
    int boff = (b == 0) ? 0 : g_bsum[b - 1];
    if (i < NNODES) {
        int r = boff + incl - d;   // exclusive prefix
        g_rowptr[i] = r;
        g_cursor[i] = r;
        g_dinv[i] = rsqrtf((float)(d > 0 ? d : 1));
        if (i == NNODES - 1) g_rowptr[NNODES] = boff + incl;
    }
}

// scatter edges into CSR buckets (sorted by dst)
__global__ void k_fill() {
    int e = blockIdx.x * blockDim.x + threadIdx.x;
    if (e >= NEDGES) return;
    int d = g_dst[e];
    int pos = atomicAdd(&g_cursor[d], 1);
    g_csrc[pos] = g_src[e];
}

// fold thetas into Wm1: wfold_k = sum_t theta_t[k] * Wm1[t*64:(t+1)*64, :]
// THETAS (D=2): t0=[3,-3,0.75], t1=[0,3,-1.5], t2=[0,0,0.75]
__global__ void k_fold(const float* __restrict__ Wm1) {
    int idx = blockIdx.x * blockDim.x + threadIdx.x;
    if (idx >= 3 * 64 * 64) return;
    int k = idx >> 12;
    int ij = idx & 4095;
    float c0, c1, c2;
    if (k == 0)      { c0 = 3.0f;  c1 = 0.0f;  c2 = 0.0f;  }
    else if (k == 1) { c0 = -3.0f; c1 = 3.0f;  c2 = 0.0f;  }
    else             { c0 = 0.75f; c1 = -1.5f; c2 = 0.75f; }
    g_wfold[idx] = c0 * Wm1[ij] + c1 * Wm1[4096 + ij] + c2 * Wm1[2 * 4096 + ij];
}

// ---------------- GEMM: C[M x 64] = act( sum_seg A_seg[M x 64] @ W_seg[64 x 64] + b ) ----------------
// RPB=32 rows/block, 256 threads, each thread: 1 col x 8 rows.
// PRESCALE: additionally write Cs = C * dinv[row].
// FUSE_FINAL: out[M x 2] = relu(...) @ Wm2 + bm2.
template <int NSEG, bool RELU, bool FUSE_FINAL, bool PRESCALE>
__global__ void __launch_bounds__(256) k_gemm(
    const float* __restrict__ A0, const float* __restrict__ A1, const float* __restrict__ A2,
    int lda,
    const float* __restrict__ W, const float* __restrict__ bias,
    float* __restrict__ C, float* __restrict__ Cs,
    const float* __restrict__ Wm2, const float* __restrict__ bm2,
    float* __restrict__ out)
{
    constexpr int KS = 64, PAD = 4, RPB = 32, R = 8;
    constexpr int LD = KS + PAD;                 // 68
    __shared__ float Ws[64 * LD];                // transposed: Ws[col][k]
    __shared__ float As[RPB * LD];
    __shared__ float Zs[FUSE_FINAL ? RPB * LD : 1];

    int tid = threadIdx.x;
    int col = tid & 63;
    int ty = tid >> 6;                           // 0..3
    int row0 = blockIdx.x * RPB;

    float acc[R];
#pragma unroll
    for (int r = 0; r < R; r++) acc[r] = 0.f;
    const float* Aseg[3] = {A0, A1, A2};

#pragma unroll
    for (int sg = 0; sg < NSEG; sg++) {
        const float* Wc = W + sg * KS * 64;
        for (int i = tid; i < KS * 64; i += 256) {
            int k = i >> 6, c = i & 63;
            Ws[c * LD + k] = Wc[i];
        }
        {
            int r = tid >> 4;            // 0..15
            int kq = tid & 15;
            const float* Ab = Aseg[sg];
            float4 v0 = *(const float4*)&Ab[(size_t)(row0 + r) * lda + kq * 4];
            float4 v1 = *(const float4*)&Ab[(size_t)(row0 + r + 16) * lda + kq * 4];
            *(float4*)&As[r * LD + kq * 4] = v0;
            *(float4*)&As[(r + 16) * LD + kq * 4] = v1;
        }
        __syncthreads();
#pragma unroll
        for (int k = 0; k < KS; k += 4) {
            float4 w = *(const float4*)&Ws[col * LD + k];
#pragma unroll
            for (int r = 0; r < R; r++) {
                float4 a = *(const float4*)&As[(ty * R + r) * LD + k];  // broadcast
                acc[r] = fmaf(a.x, w.x, acc[r]);
                acc[r] = fmaf(a.y, w.y, acc[r]);
                acc[r] = fmaf(a.z, w.z, acc[r]);
                acc[r] = fmaf(a.w, w.w, acc[r]);
            }
        }
        __syncthreads();
    }

    float bv = __ldg(&bias[col]);
    if (!FUSE_FINAL) {
#pragma unroll
        for (int r = 0; r < R; r++) {
            int row = row0 + ty * R + r;
            float v = acc[r] + bv;
            if (RELU) v = fmaxf(v, 0.f);
            C[(size_t)row * 64 + col] = v;
            if (PRESCALE) Cs[(size_t)row * 64 + col] = v * g_dinv[row];
        }
    } else {
#pragma unroll
        for (int r = 0; r < R; r++) {
            float v = fmaxf(acc[r] + bv, 0.f);
            Zs[(ty * R + r) * LD + col] = v;
        }
        __syncthreads();
        if (tid < RPB * 2) {
            int r = tid >> 1, c2 = tid & 1;
            float sacc = __ldg(&bm2[c2]);
#pragma unroll
            for (int c = 0; c < 64; c++)
                sacc = fmaf(Zs[r * LD + c], __ldg(&Wm2[c * 2 + c2]), sacc);
            out[(size_t)(row0 + r) * 2 + c2] = sacc;
        }
    }
}

// ---------------- propagation ----------------
// fout[n] = fin[n] - dinv[n] * sum_{s in in(n)} fins[s]      (fins already prescaled by dinv)
// optional: fouts[n] = fout[n] * dinv[n]  for the next hop
template <bool OUT_SCALED>
__global__ void __launch_bounds__(256) k_prop(const float* __restrict__ fin,
                                              const float* __restrict__ fins,
                                              float* __restrict__ fout,
                                              float* __restrict__ fouts)
{
    int n = (blockIdx.x * blockDim.x + threadIdx.x) >> 5;
    int lane = threadIdx.x & 31;
    int start = g_rowptr[n];
    int end = g_rowptr[n + 1];

    float ax = 0.f, ay = 0.f;
    for (int i = start; i < end; i += 32) {
        int cnt = min(32, end - i);
        int s = 0;
        if (lane < cnt) s = g_csrc[i + lane];
        int j = 0;
        for (; j + 4 <= cnt; j += 4) {
            int s0 = __shfl_sync(0xffffffffu, s, j);
            int s1 = __shfl_sync(0xffffffffu, s, j + 1);
            int s2 = __shfl_sync(0xffffffffu, s, j + 2);
            int s3 = __shfl_sync(0xffffffffu, s, j + 3);
            float2 v0 = *(const float2*)&fins[(size_t)s0 * 64 + lane * 2];
            float2 v1 = *(const float2*)&fins[(size_t)s1 * 64 + lane * 2];
            float2 v2 = *(const float2*)&fins[(size_t)s2 * 64 + lane * 2];
            float2 v3 = *(const float2*)&fins[(size_t)s3 * 64 + lane * 2];
            ax += (v0.x + v1.x) + (v2.x + v3.x);
            ay += (v0.y + v1.y) + (v2.y + v3.y);
        }
        for (; j < cnt; j++) {
            int sj = __shfl_sync(0xffffffffu, s, j);
            float2 v = *(const float2*)&fins[(size_t)sj * 64 + lane * 2];
            ax += v.x;
            ay += v.y;
        }
    }
    float dn = g_dinv[n];
    float2 cur = *(const float2*)&fin[(size_t)n * 64 + lane * 2];
    float2 o = make_float2(cur.x - ax * dn, cur.y - ay * dn);
    *(float2*)&fout[(size_t)n * 64 + lane * 2] = o;
    if (OUT_SCALED) {
        float2 os = make_float2(o.x * dn, o.y * dn);
        *(float2*)&fouts[(size_t)n * 64 + lane * 2] = os;
    }
}

// ---------------- launch ----------------
extern "C" void kernel_launch(void* const* d_in, const int* in_sizes, int n_in,
                              void* d_out, int out_size)
{
    const float* x   = (const float*)d_in[0];
    const void*  ei  = d_in[1];
    const float* W1  = (const float*)d_in[2];
    const float* b1  = (const float*)d_in[3];
    const float* W2  = (const float*)d_in[4];
    const float* b2  = (const float*)d_in[5];
    const float* Wm1 = (const float*)d_in[6];
    const float* bm1 = (const float*)d_in[7];
    const float* Wm2 = (const float*)d_in[8];
    const float* bm2 = (const float*)d_in[9];
    float* out = (float*)d_out;

    float *ph1, *pf0, *pf0s, *pf1, *pf1s, *pf2, *pwf;
    cudaGetSymbolAddress((void**)&ph1, g_h1);
    cudaGetSymbolAddress((void**)&pf0, g_f0);
    cudaGetSymbolAddress((void**)&pf0s, g_f0s);
    cudaGetSymbolAddress((void**)&pf1, g_f1);
    cudaGetSymbolAddress((void**)&pf1s, g_f1s);
    cudaGetSymbolAddress((void**)&pf2, g_f2);
    cudaGetSymbolAddress((void**)&pwf, g_wfold);

    // graph prep
    k_init<<<(NNODES + 255) / 256, 256>>>();
    k_detect<<<256, 256>>>((const int*)ei);
    k_convert_degree<<<NEDGES / 256, 256>>>(ei);
    k_blocksum<<<NBLK, SCAN_B>>>();
    k_scan_bsums<<<1, 512>>>();
    k_rowptr<<<NBLK, SCAN_B>>>();
    k_fill<<<NEDGES / 256, 256>>>();
    k_fold<<<(3 * 64 * 64 + 255) / 256, 256>>>(Wm1);

    // MLP: h1 = relu(x @ W1 + b1)  (K=128 -> two 64-K segments)
    k_gemm<2, true, false, false><<<NNODES / 32, 256>>>(x, x + 64, nullptr, 128, W1, b1,
                                                        ph1, nullptr, nullptr, nullptr, nullptr);
    // f0 = relu(h1 @ W2 + b2), f0s = f0 * dinv
    k_gemm<1, true, false, true><<<NNODES / 32, 256>>>(ph1, nullptr, nullptr, 64, W2, b2,
                                                       pf0, pf0s, nullptr, nullptr, nullptr);
    // propagation (shared across all thetas): f1 = P f0, f2 = P f1
    k_prop<true><<<(NNODES * 32) / 256, 256>>>(pf0, pf0s, pf1, pf1s);
    k_prop<false><<<(NNODES * 32) / 256, 256>>>(pf1, pf1s, pf2, nullptr);

    // head: out = relu(f0@Wf0 + f1@Wf1 + f2@Wf2 + bm1) @ Wm2 + bm2 (fused)
    k_gemm<3, true, true, false><<<NNODES / 32, 256>>>(pf0, pf1, pf2, 64, pwf, bm1,
                                                       nullptr, nullptr, Wm2, bm2, out);
}

// round 4
// speedup vs baseline: 2.3988x; 1.3773x over previous
#include <cuda_runtime.h>
#include <cuda_fp16.h>
#include <cstdint>

#define NNODES 100000
#define NEDGES 1600000
#define NPAD   100096          // 782 * 128
#define NTILES 782
#define SCAN_B 256
#define NBLK ((NNODES + SCAN_B - 1) / SCAN_B)   // 391

// ---------------- static device scratch ----------------
__device__ __half g_xh[NPAD * 128], g_xl[NPAD * 128];
__device__ __half g_h1h[NPAD * 64], g_h1l[NPAD * 64];
__device__ __half g_f0h[NPAD * 64], g_f0l[NPAD * 64], g_f0s[NPAD * 64];
__device__ __half g_f1h[NPAD * 64], g_f1l[NPAD * 64], g_f1s[NPAD * 64];
__device__ __half g_f2h[NPAD * 64], g_f2l[NPAD * 64];
__device__ int   g_src[NEDGES], g_dst[NEDGES], g_csrc[NEDGES];
__device__ int   g_deg[NNODES], g_rowptr[NNODES + 1], g_cursor[NNODES], g_bsum[NBLK];
__device__ float g_dinv[NPAD];             // tail stays zero
__device__ float g_wfold[3 * 64 * 64];
__device__ int   g_flag;                   // 0 = int64 edges, 1 = int32

// ---------------- helpers ----------------
__device__ __forceinline__ uint32_t smem_u32(const void* p) {
    uint32_t a;
    asm("{ .reg .u64 t; cvta.to.shared.u64 t, %1; cvt.u32.u64 %0, t; }" : "=r"(a) : "l"(p));
    return a;
}
__device__ __forceinline__ uint32_t pack2h(float a, float b) {
    __half2 h = __floats2half2_rn(a, b);
    return *reinterpret_cast<uint32_t*>(&h);
}

#define LDSM4(d, a)                                                              \
    asm volatile("ldmatrix.sync.aligned.m8n8.x4.shared.b16 {%0,%1,%2,%3}, [%4];" \
                 : "=r"((d)[0]), "=r"((d)[1]), "=r"((d)[2]), "=r"((d)[3]) : "r"(a))
#define LDSM2(d, a)                                                              \
    asm volatile("ldmatrix.sync.aligned.m8n8.x2.shared.b16 {%0,%1}, [%2];"       \
                 : "=r"((d)[0]), "=r"((d)[1]) : "r"(a))
#define MMA(c, a, b)                                                             \
    asm volatile("mma.sync.aligned.m16n8k16.row.col.f32.f16.f16.f32 "            \
                 "{%0,%1,%2,%3},{%4,%5,%6,%7},{%8,%9},{%0,%1,%2,%3};"            \
                 : "+f"((c)[0]), "+f"((c)[1]), "+f"((c)[2]), "+f"((c)[3])        \
                 : "r"((a)[0]), "r"((a)[1]), "r"((a)[2]), "r"((a)[3]),           \
                   "r"((b)[0]), "r"((b)[1]))

// ---------------- prep kernels ----------------
__global__ void k_init() {
    int i = blockIdx.x * blockDim.x + threadIdx.x;
    if (i < NNODES) g_deg[i] = 0;
    if (i == 0) g_flag = 0;
}
__global__ void k_detect(const int* __restrict__ e32) {
    int i = blockIdx.x * blockDim.x + threadIdx.x;
    int stride = gridDim.x * blockDim.x;
    for (int e = i; e < NEDGES; e += stride)
        if (e32[2 * e + 1] != 0) { g_flag = 1; break; }
}
__global__ void k_convert_degree(const void* __restrict__ eptr) {
    int e = blockIdx.x * blockDim.x + threadIdx.x;
    if (e >= NEDGES) return;
    int s, d;
    if (g_flag == 0) {
        const long long* p = (const long long*)eptr;
        s = (int)p[e]; d = (int)p[NEDGES + e];
    } else {
        const int* p = (const int*)eptr;
        s = p[e]; d = p[NEDGES + e];
    }
    g_src[e] = s; g_dst[e] = d;
    atomicAdd(&g_deg[d], 1);
}
__global__ void k_blocksum() {
    __shared__ int sh[SCAN_B];
    int i = blockIdx.x * SCAN_B + threadIdx.x;
    sh[threadIdx.x] = (i < NNODES) ? g_deg[i] : 0;
    __syncthreads();
    for (int off = SCAN_B / 2; off > 0; off >>= 1) {
        if (threadIdx.x < off) sh[threadIdx.x] += sh[threadIdx.x + off];
        __syncthreads();
    }
    if (threadIdx.x == 0) g_bsum[blockIdx.x] = sh[0];
}
__global__ void k_scan_bsums() {
    __shared__ int sh[512];
    int t = threadIdx.x;
    sh[t] = (t < NBLK) ? g_bsum[t] : 0;
    __syncthreads();
    for (int off = 1; off < 512; off <<= 1) {
        int v = (t >= off) ? sh[t - off] : 0;
        __syncthreads();
        sh[t] += v;
        __syncthreads();
    }
    if (t < NBLK) g_bsum[t] = sh[t];
}
__global__ void k_rowptr() {
    __shared__ int sh[SCAN_B];
    int b = blockIdx.x;
    int i = b * SCAN_B + threadIdx.x;
    int d = (i < NNODES) ? g_deg[i] : 0;
    sh[threadIdx.x] = d;
    __syncthreads();
    for (int off = 1; off < SCAN_B; off <<= 1) {
        int v = (threadIdx.x >= off) ? sh[threadIdx.x - off] : 0;
        __syncthreads();
        sh[threadIdx.x] += v;
        __syncthreads();
    }
    int incl = sh[threadIdx.x];
    int boff = (b == 0) ? 0 : g_bsum[b - 1];
    if (i < NNODES) {
        int r = boff + incl - d;
        g_rowptr[i] = r;
        g_cursor[i] = r;
        g_dinv[i] = rsqrtf((float)(d > 0 ? d : 1));
        if (i == NNODES - 1) g_rowptr[NNODES] = boff + incl;
    }
}
__global__ void k_fill() {
    int e = blockIdx.x * blockDim.x + threadIdx.x;
    if (e >= NEDGES) return;
    int d = g_dst[e];
    int pos = atomicAdd(&g_cursor[d], 1);
    g_csrc[pos] = g_src[e];
}
// fold thetas: t0=[3,-3,0.75], t1=[0,3,-1.5], t2=[0,0,0.75]
__global__ void k_fold(const float* __restrict__ Wm1) {
    int idx = blockIdx.x * blockDim.x + threadIdx.x;
    if (idx >= 3 * 64 * 64) return;
    int k = idx >> 12, ij = idx & 4095;
    float c0, c1, c2;
    if (k == 0)      { c0 = 3.0f;  c1 = 0.0f;  c2 = 0.0f;  }
    else if (k == 1) { c0 = -3.0f; c1 = 3.0f;  c2 = 0.0f;  }
    else             { c0 = 0.75f; c1 = -1.5f; c2 = 0.75f; }
    g_wfold[idx] = c0 * Wm1[ij] + c1 * Wm1[4096 + ij] + c2 * Wm1[2 * 4096 + ij];
}
// x -> fp16 hi/lo
__global__ void k_half(const float* __restrict__ x) {
    int i = blockIdx.x * blockDim.x + threadIdx.x;
    if (i >= NNODES * 128) return;
    float v = x[i];
    __half h = __float2half_rn(v);
    g_xh[i] = h;
    g_xl[i] = __float2half_rn(v - __half2float(h));
}

// ---------------- HMMA GEMM ----------------
// C[128x64] tile = act( sum_seg A_seg[128x64] @ W_seg[64x64] + bias )
// fp16 hi/lo split, fp32 accumulate via mma.sync. 8 warps: wy=warp&3 (32 rows), wx=warp>>2 (32 cols).
// MODE 0: write hi/lo C. MODE 1: + prescaled (C*dinv). MODE 2: fused @Wm2+bm2 head.
#define LDH 72     // halves per staged row (stride 144B -> conflict-free ldmatrix)
#define LDF 68     // f32 stride for epilogue tile
#define OFF_BIAS 0
#define OFF_WM2  256
#define OFF_CT   768                     // overlaps AH/AL (dead by epilogue)
#define OFF_AH   768
#define OFF_AL   (OFF_AH + 128 * LDH * 2)    // 19200
#define OFF_WH   (OFF_AL + 128 * LDH * 2)    // 37632
#define OFF_WL   (OFF_WH + 64 * LDH * 2)     // 46848
#define SMEM_SZ  (OFF_WL + 64 * LDH * 2)     // 56064

template <int NSEG, int MODE>
__global__ void __launch_bounds__(256) k_mma(
    const __half* __restrict__ Ah0, const __half* __restrict__ Al0,
    const __half* __restrict__ Ah1, const __half* __restrict__ Al1,
    const __half* __restrict__ Ah2, const __half* __restrict__ Al2,
    int lda,
    const float* __restrict__ W, const float* __restrict__ bias,
    __half* __restrict__ Ch, __half* __restrict__ Cl, __half* __restrict__ Cs,
    const float* __restrict__ Wm2, const float* __restrict__ bm2,
    float* __restrict__ out)
{
    extern __shared__ char smem[];
    uint32_t sb = smem_u32(smem);
    float* sbias = (float*)(smem + OFF_BIAS);
    float* swm2  = (float*)(smem + OFF_WM2);
    __half* sAh = (__half*)(smem + OFF_AH);
    __half* sAl = (__half*)(smem + OFF_AL);
    __half* sWh = (__half*)(smem + OFF_WH);
    __half* sWl = (__half*)(smem + OFF_WL);

    int tid = threadIdx.x;
    int warp = tid >> 5, lane = tid & 31;
    int wy = warp & 3, wx = warp >> 2;
    int row0 = blockIdx.x * 128;

    if (tid < 64) sbias[tid] = bias[tid];
    if (MODE == 2 && tid < 128) swm2[tid] = Wm2[tid];

    float acc[2][4][4];
#pragma unroll
    for (int mi = 0; mi < 2; mi++)
#pragma unroll
        for (int ni = 0; ni < 4; ni++)
#pragma unroll
            for (int j = 0; j < 4; j++) acc[mi][ni][j] = 0.f;

    const __half* Ah[3] = {Ah0, Ah1, Ah2};
    const __half* Al[3] = {Al0, Al1, Al2};

    // ldmatrix lane address components
    const int arow = wy * 32 + (lane & 7) + ((lane >> 3) & 1) * 8;
    const int acol = ((lane >> 4) & 1) * 8;
    const int brow = wx * 32 + (lane & 7);
    const int bcol = ((lane >> 3) & 1) * 8;

#pragma unroll
    for (int sg = 0; sg < NSEG; sg++) {
        __syncthreads();
        // stage A hi/lo
        {
            const __half* pa = Ah[sg];
            const __half* pl = Al[sg];
#pragma unroll
            for (int it = 0; it < 4; it++) {
                int idx = tid + it * 256;        // 0..1023
                int row = idx >> 3;
                int c8 = (idx & 7) * 8;
                size_t gofs = (size_t)(row0 + row) * lda + c8;
                *(uint4*)&sAh[row * LDH + c8] = *(const uint4*)(pa + gofs);
                *(uint4*)&sAl[row * LDH + c8] = *(const uint4*)(pl + gofs);
            }
        }
        // stage W hi/lo transposed [n][k]
        {
            const float* Wc = W + sg * 4096;
            for (int i = tid; i < 4096; i += 256) {
                int k = i >> 6, n = i & 63;
                float w = Wc[i];
                __half hh = __float2half_rn(w);
                sWh[n * LDH + k] = hh;
                sWl[n * LDH + k] = __float2half_rn(w - __half2float(hh));
            }
        }
        __syncthreads();
#pragma unroll
        for (int kc = 0; kc < 64; kc += 16) {
            uint32_t ah[2][4], al[2][4];
#pragma unroll
            for (int mi = 0; mi < 2; mi++) {
                uint32_t aa = sb + OFF_AH + ((arow + mi * 16) * LDH + kc + acol) * 2;
                LDSM4(ah[mi], aa);
                LDSM4(al[mi], aa + (OFF_AL - OFF_AH));
            }
#pragma unroll
            for (int ni = 0; ni < 4; ni++) {
                uint32_t wh[2], wl[2];
                uint32_t ba = sb + OFF_WH + ((brow + ni * 8) * LDH + kc + bcol) * 2;
                LDSM2(wh, ba);
                LDSM2(wl, ba + (OFF_WL - OFF_WH));
#pragma unroll
                for (int mi = 0; mi < 2; mi++) {
                    MMA(acc[mi][ni], ah[mi], wh);
                    MMA(acc[mi][ni], al[mi], wh);
                    MMA(acc[mi][ni], ah[mi], wl);
                }
            }
        }
    }

    // ---- epilogue: park raw acc in smem (reuses A staging), then convert ----
    __syncthreads();
    float* sC = (float*)(smem + OFF_CT);
    {
        int g = lane >> 2, qp = (lane & 3) * 2;
#pragma unroll
        for (int mi = 0; mi < 2; mi++)
#pragma unroll
            for (int ni = 0; ni < 4; ni++) {
                int r = wy * 32 + mi * 16 + g;
                int c = wx * 32 + ni * 8 + qp;
                *(float2*)&sC[r * LDF + c]       = make_float2(acc[mi][ni][0], acc[mi][ni][1]);
                *(float2*)&sC[(r + 8) * LDF + c] = make_float2(acc[mi][ni][2], acc[mi][ni][3]);
            }
    }
    __syncthreads();

    if (MODE != 2) {
#pragma unroll
        for (int it = 0; it < 4; it++) {
            int idx = tid + it * 256;
            int row = idx >> 3;
            int c8 = (idx & 7) * 8;
            float v[8];
#pragma unroll
            for (int j = 0; j < 8; j++)
                v[j] = fmaxf(sC[row * LDF + c8 + j] + sbias[c8 + j], 0.f);
            uint4 ph, pl2;
            float lo[8];
#pragma unroll
            for (int j = 0; j < 8; j++) {
                __half h = __float2half_rn(v[j]);
                lo[j] = v[j] - __half2float(h);
            }
            ph.x = pack2h(v[0], v[1]); ph.y = pack2h(v[2], v[3]);
            ph.z = pack2h(v[4], v[5]); ph.w = pack2h(v[6], v[7]);
            pl2.x = pack2h(lo[0], lo[1]); pl2.y = pack2h(lo[2], lo[3]);
            pl2.z = pack2h(lo[4], lo[5]); pl2.w = pack2h(lo[6], lo[7]);
            size_t base = (size_t)(row0 + row) * 64 + c8;
            *(uint4*)(Ch + base) = ph;
            *(uint4*)(Cl + base) = pl2;
            if (MODE == 1) {
                float dn = g_dinv[row0 + row];
                uint4 ps;
                ps.x = pack2h(v[0] * dn, v[1] * dn); ps.y = pack2h(v[2] * dn, v[3] * dn);
                ps.z = pack2h(v[4] * dn, v[5] * dn); ps.w = pack2h(v[6] * dn, v[7] * dn);
                *(uint4*)(Cs + base) = ps;
            }
        }
    } else {
        int r = tid >> 1, c2 = tid & 1;
        float s = 0.f;
#pragma unroll
        for (int c = 0; c < 64; c++)
            s = fmaf(fmaxf(sC[r * LDF + c] + sbias[c], 0.f), swm2[c * 2 + c2], s);
        if (row0 + r < NNODES)
            out[(size_t)(row0 + r) * 2 + c2] = s + __ldg(&bm2[c2]);
    }
}

// ---------------- propagation (fp16 gather, exact diagonal) ----------------
// fout = (finh+finl) - dinv[n] * sum_{s in in(n)} fins[s]
template <bool OUT_SCALED>
__global__ void __launch_bounds__(256) k_prop(
    const __half* __restrict__ finh, const __half* __restrict__ finl,
    const __half* __restrict__ fins,
    __half* __restrict__ fouth, __half* __restrict__ foutl, __half* __restrict__ fouts)
{
    int n = (blockIdx.x * blockDim.x + threadIdx.x) >> 5;
    int lane = threadIdx.x & 31;
    int start = g_rowptr[n];
    int end = g_rowptr[n + 1];

    float ax = 0.f, ay = 0.f;
    for (int i = start; i < end; i += 32) {
        int cnt = min(32, end - i);
        int s = 0;
        if (lane < cnt) s = g_csrc[i + lane];
        int j = 0;
        for (; j + 4 <= cnt; j += 4) {
            int s0 = __shfl_sync(0xffffffffu, s, j);
            int s1 = __shfl_sync(0xffffffffu, s, j + 1);
            int s2 = __shfl_sync(0xffffffffu, s, j + 2);
            int s3 = __shfl_sync(0xffffffffu, s, j + 3);
            float2 v0 = __half22float2(*(const __half2*)&fins[(size_t)s0 * 64 + lane * 2]);
            float2 v1 = __half22float2(*(const __half2*)&fins[(size_t)s1 * 64 + lane * 2]);
            float2 v2 = __half22float2(*(const __half2*)&fins[(size_t)s2 * 64 + lane * 2]);
            float2 v3 = __half22float2(*(const __half2*)&fins[(size_t)s3 * 64 + lane * 2]);
            ax += (v0.x + v1.x) + (v2.x + v3.x);
            ay += (v0.y + v1.y) + (v2.y + v3.y);
        }
        for (; j < cnt; j++) {
            int sj = __shfl_sync(0xffffffffu, s, j);
            float2 v = __half22float2(*(const __half2*)&fins[(size_t)sj * 64 + lane * 2]);
            ax += v.x;
            ay += v.y;
        }
    }
    float dn = g_dinv[n];
    size_t base = (size_t)n * 64 + lane * 2;
    float2 ch = __half22float2(*(const __half2*)&finh[base]);
    float2 cl = __half22float2(*(const __half2*)&finl[base]);
    float ox = (ch.x + cl.x) - ax * dn;
    float oy = (ch.y + cl.y) - ay * dn;
    __half hx = __float2half_rn(ox), hy = __float2half_rn(oy);
    *(uint32_t*)&fouth[base] = pack2h(ox, oy);
    *(uint32_t*)&foutl[base] = pack2h(ox - __half2float(hx), oy - __half2float(hy));
    if (OUT_SCALED)
        *(uint32_t*)&fouts[base] = pack2h(ox * dn, oy * dn);
}

// ---------------- launch ----------------
extern "C" void kernel_launch(void* const* d_in, const int* in_sizes, int n_in,
                              void* d_out, int out_size)
{
    const float* x   = (const float*)d_in[0];
    const void*  ei  = d_in[1];
    const float* W1  = (const float*)d_in[2];
    const float* b1  = (const float*)d_in[3];
    const float* W2  = (const float*)d_in[4];
    const float* b2  = (const float*)d_in[5];
    const float* Wm1 = (const float*)d_in[6];
    const float* bm1 = (const float*)d_in[7];
    const float* Wm2 = (const float*)d_in[8];
    const float* bm2 = (const float*)d_in[9];
    float* out = (float*)d_out;

    __half *xh, *xl, *h1h, *h1l, *f0h, *f0l, *f0s, *f1h, *f1l, *f1s, *f2h, *f2l;
    float *pwf;
    cudaGetSymbolAddress((void**)&xh, g_xh);
    cudaGetSymbolAddress((void**)&xl, g_xl);
    cudaGetSymbolAddress((void**)&h1h, g_h1h);
    cudaGetSymbolAddress((void**)&h1l, g_h1l);
    cudaGetSymbolAddress((void**)&f0h, g_f0h);
    cudaGetSymbolAddress((void**)&f0l, g_f0l);
    cudaGetSymbolAddress((void**)&f0s, g_f0s);
    cudaGetSymbolAddress((void**)&f1h, g_f1h);
    cudaGetSymbolAddress((void**)&f1l, g_f1l);
    cudaGetSymbolAddress((void**)&f1s, g_f1s);
    cudaGetSymbolAddress((void**)&f2h, g_f2h);
    cudaGetSymbolAddress((void**)&f2l, g_f2l);
    cudaGetSymbolAddress((void**)&pwf, g_wfold);

    cudaFuncSetAttribute(k_mma<2, 0>, cudaFuncAttributeMaxDynamicSharedMemorySize, SMEM_SZ);
    cudaFuncSetAttribute(k_mma<1, 1>, cudaFuncAttributeMaxDynamicSharedMemorySize, SMEM_SZ);
    cudaFuncSetAttribute(k_mma<3, 2>, cudaFuncAttributeMaxDynamicSharedMemorySize, SMEM_SZ);

    // graph prep
    k_init<<<(NNODES + 255) / 256, 256>>>();
    k_detect<<<256, 256>>>((const int*)ei);
    k_convert_degree<<<NEDGES / 256, 256>>>(ei);
    k_blocksum<<<NBLK, SCAN_B>>>();
    k_scan_bsums<<<1, 512>>>();
    k_rowptr<<<NBLK, SCAN_B>>>();
    k_fill<<<NEDGES / 256, 256>>>();
    k_fold<<<(3 * 64 * 64 + 255) / 256, 256>>>(Wm1);
    k_half<<<(NNODES * 128 + 255) / 256, 256>>>(x);

    // h1 = relu(x @ W1 + b1)   (K=128: 2 segments)
    k_mma<2, 0><<<NTILES, 256, SMEM_SZ>>>(xh, xl, xh + 64, xl + 64, nullptr, nullptr,
                                          128, W1, b1, h1h, h1l, nullptr,
                                          nullptr, nullptr, nullptr);
    // f0 = relu(h1 @ W2 + b2), f0s = f0 * dinv
    k_mma<1, 1><<<NTILES, 256, SMEM_SZ>>>(h1h, h1l, nullptr, nullptr, nullptr, nullptr,
                                          64, W2, b2, f0h, f0l, f0s,
                                          nullptr, nullptr, nullptr);
    // f1 = P f0, f2 = P f1
    k_prop<true><<<(NNODES * 32) / 256, 256>>>(f0h, f0l, f0s, f1h, f1l, f1s);
    k_prop<false><<<(NNODES * 32) / 256, 256>>>(f1h, f1l, f1s, f2h, f2l, nullptr);

    // head: out = relu(f0@Wf0 + f1@Wf1 + f2@Wf2 + bm1) @ Wm2 + bm2
    k_mma<3, 2><<<NTILES, 256, SMEM_SZ>>>(f0h, f0l, f1h, f1l, f2h, f2l,
                                          64, pwf, bm1, nullptr, nullptr, nullptr,
                                          Wm2, bm2, out);
}

// round 5
// speedup vs baseline: 2.7426x; 1.1433x over previous
#include <cuda_runtime.h>
#include <cuda_fp16.h>
#include <cstdint>

#define NNODES 100000
#define NEDGES 1600000
#define NPAD   100096          // 782 * 128
#define NTILES 782
#define SCAN_B 256
#define NBLK ((NNODES + SCAN_B - 1) / SCAN_B)   // 391

// ---------------- static device scratch ----------------
__device__ float  g_h1[NPAD * 64];
__device__ float  g_f0[NPAD * 64], g_f1[NPAD * 64], g_f2[NPAD * 64];
__device__ __half g_f0s[NPAD * 64], g_f1s[NPAD * 64];
__device__ int    g_csrc[NEDGES];
__device__ int    g_deg[NNODES], g_rowptr[NNODES + 1], g_cursor[NNODES], g_bsum[NBLK];
__device__ float  g_dinv[NPAD];            // tail stays zero
__device__ float  g_wfold[3 * 64 * 64];
__device__ int    g_flag;                  // 0 = int64 edges, 1 = int32

// ---------------- helpers ----------------
__device__ __forceinline__ uint32_t smem_u32(const void* p) {
    uint32_t a;
    asm("{ .reg .u64 t; cvta.to.shared.u64 t, %1; cvt.u32.u64 %0, t; }" : "=r"(a) : "l"(p));
    return a;
}
__device__ __forceinline__ uint32_t pack2h(float a, float b) {
    __half2 h = __floats2half2_rn(a, b);
    return *reinterpret_cast<uint32_t*>(&h);
}

#define LDSM4(d, a)                                                              \
    asm volatile("ldmatrix.sync.aligned.m8n8.x4.shared.b16 {%0,%1,%2,%3}, [%4];" \
                 : "=r"((d)[0]), "=r"((d)[1]), "=r"((d)[2]), "=r"((d)[3]) : "r"(a))
#define LDSM2(d, a)                                                              \
    asm volatile("ldmatrix.sync.aligned.m8n8.x2.shared.b16 {%0,%1}, [%2];"       \
                 : "=r"((d)[0]), "=r"((d)[1]) : "r"(a))
#define MMA(c, a, b)                                                             \
    asm volatile("mma.sync.aligned.m16n8k16.row.col.f32.f16.f16.f32 "            \
                 "{%0,%1,%2,%3},{%4,%5,%6,%7},{%8,%9},{%0,%1,%2,%3};"            \
                 : "+f"((c)[0]), "+f"((c)[1]), "+f"((c)[2]), "+f"((c)[3])        \
                 : "r"((a)[0]), "r"((a)[1]), "r"((a)[2]), "r"((a)[3]),           \
                   "r"((b)[0]), "r"((b)[1]))

// ---------------- prep kernels ----------------
__global__ void k_detect(const int* __restrict__ e32) {
    int i = blockIdx.x * blockDim.x + threadIdx.x;
    int stride = gridDim.x * blockDim.x;
    for (int e = i; e < NEDGES; e += stride)
        if (e32[2 * e + 1] != 0) { g_flag = 1; break; }
}
__global__ void k_degree(const void* __restrict__ eptr) {
    int e = blockIdx.x * blockDim.x + threadIdx.x;
    if (e >= NEDGES) return;
    int d;
    if (g_flag == 0) d = (int)((const long long*)eptr)[NEDGES + e];
    else             d = ((const int*)eptr)[NEDGES + e];
    atomicAdd(&g_deg[d], 1);
}
__global__ void k_blocksum() {
    __shared__ int sh[SCAN_B];
    int i = blockIdx.x * SCAN_B + threadIdx.x;
    sh[threadIdx.x] = (i < NNODES) ? g_deg[i] : 0;
    __syncthreads();
    for (int off = SCAN_B / 2; off > 0; off >>= 1) {
        if (threadIdx.x < off) sh[threadIdx.x] += sh[threadIdx.x + off];
        __syncthreads();
    }
    if (threadIdx.x == 0) g_bsum[blockIdx.x] = sh[0];
}
__global__ void k_scan_bsums() {
    __shared__ int sh[512];
    int t = threadIdx.x;
    sh[t] = (t < NBLK) ? g_bsum[t] : 0;
    __syncthreads();
    for (int off = 1; off < 512; off <<= 1) {
        int v = (t >= off) ? sh[t - off] : 0;
        __syncthreads();
        sh[t] += v;
        __syncthreads();
    }
    if (t < NBLK) g_bsum[t] = sh[t];
}
__global__ void k_rowptr() {
    __shared__ int sh[SCAN_B];
    int b = blockIdx.x;
    int i = b * SCAN_B + threadIdx.x;
    int d = (i < NNODES) ? g_deg[i] : 0;
    sh[threadIdx.x] = d;
    __syncthreads();
    for (int off = 1; off < SCAN_B; off <<= 1) {
        int v = (threadIdx.x >= off) ? sh[threadIdx.x - off] : 0;
        __syncthreads();
        sh[threadIdx.x] += v;
        __syncthreads();
    }
    int incl = sh[threadIdx.x];
    int boff = (b == 0) ? 0 : g_bsum[b - 1];
    if (i < NNODES) {
        int r = boff + incl - d;
        g_rowptr[i] = r;
        g_cursor[i] = r;
        g_dinv[i] = rsqrtf((float)(d > 0 ? d : 1));
        if (i == NNODES - 1) g_rowptr[NNODES] = boff + incl;
    }
}
__global__ void k_fill(const void* __restrict__ eptr) {
    int e = blockIdx.x * blockDim.x + threadIdx.x;
    if (e >= NEDGES) return;
    int s, d;
    if (g_flag == 0) {
        const long long* p = (const long long*)eptr;
        s = (int)p[e]; d = (int)p[NEDGES + e];
    } else {
        const int* p = (const int*)eptr;
        s = p[e]; d = p[NEDGES + e];
    }
    int pos = atomicAdd(&g_cursor[d], 1);
    g_csrc[pos] = s;
}
// fold thetas: t0=[3,-3,0.75], t1=[0,3,-1.5], t2=[0,0,0.75]
__global__ void k_fold(const float* __restrict__ Wm1) {
    int idx = blockIdx.x * blockDim.x + threadIdx.x;
    if (idx >= 3 * 64 * 64) return;
    int k = idx >> 12, ij = idx & 4095;
    float c0, c1, c2;
    if (k == 0)      { c0 = 3.0f;  c1 = 0.0f;  c2 = 0.0f;  }
    else if (k == 1) { c0 = -3.0f; c1 = 3.0f;  c2 = 0.0f;  }
    else             { c0 = 0.75f; c1 = -1.5f; c2 = 0.75f; }
    g_wfold[idx] = c0 * Wm1[ij] + c1 * Wm1[4096 + ij] + c2 * Wm1[2 * 4096 + ij];
}

// ---------------- HMMA GEMM ----------------
// C[128x64] = act( sum_seg A_seg[128x64](fp32) @ W_seg[64x64](fp32) + bias )
// fp16 hi/lo split in staging registers, fp32 accumulate via mma.sync.
// 8 warps: wy=warp&3 (32 rows), wx=warp>>2 (32 cols).
// MODE 0: write fp32 C. MODE 1: + fp16 prescaled (C*dinv). MODE 2: fused @Wm2+bm2 head.
#define LDH 72     // halves per staged row (144B stride -> conflict-free ldmatrix)
#define LDF 68     // f32 stride for epilogue tile
#define OFF_BIAS 0
#define OFF_WM2  256
#define OFF_CT   768                          // overlaps AH/AL (dead by epilogue)
#define OFF_AH   768
#define OFF_AL   (OFF_AH + 128 * LDH * 2)     // 19200
#define OFF_WH   (OFF_AL + 128 * LDH * 2)     // 37632
#define OFF_WL   (OFF_WH + 64 * LDH * 2)      // 46848
#define SMEM_SZ  (OFF_WL + 64 * LDH * 2)      // 56064

template <int NSEG, int MODE>
__global__ void __launch_bounds__(256) k_mma(
    const float* __restrict__ A0, const float* __restrict__ A1, const float* __restrict__ A2,
    int lda,
    const float* __restrict__ W, const float* __restrict__ bias,
    float* __restrict__ C, __half* __restrict__ Cs,
    const float* __restrict__ Wm2, const float* __restrict__ bm2,
    float* __restrict__ out)
{
    extern __shared__ char smem[];
    uint32_t sb = smem_u32(smem);
    float* sbias = (float*)(smem + OFF_BIAS);
    float* swm2  = (float*)(smem + OFF_WM2);
    __half* sAh = (__half*)(smem + OFF_AH);
    __half* sAl = (__half*)(smem + OFF_AL);
    __half* sWh = (__half*)(smem + OFF_WH);
    __half* sWl = (__half*)(smem + OFF_WL);

    int tid = threadIdx.x;
    int warp = tid >> 5, lane = tid & 31;
    int wy = warp & 3, wx = warp >> 2;
    int row0 = blockIdx.x * 128;

    if (tid < 64) sbias[tid] = bias[tid];
    if (MODE == 2 && tid < 128) swm2[tid] = Wm2[tid];

    float acc[2][4][4];
#pragma unroll
    for (int mi = 0; mi < 2; mi++)
#pragma unroll
        for (int ni = 0; ni < 4; ni++)
#pragma unroll
            for (int j = 0; j < 4; j++) acc[mi][ni][j] = 0.f;

    const float* Aseg[3] = {A0, A1, A2};

    const int arow = wy * 32 + (lane & 7) + ((lane >> 3) & 1) * 8;
    const int acol = ((lane >> 4) & 1) * 8;
    const int brow = wx * 32 + (lane & 7);
    const int bcol = ((lane >> 3) & 1) * 8;

#pragma unroll
    for (int sg = 0; sg < NSEG; sg++) {
        __syncthreads();
        // stage A: read fp32, split hi/lo in registers
        {
            const float* pa = Aseg[sg];
#pragma unroll
            for (int it = 0; it < 4; it++) {
                int idx = tid + it * 256;        // 0..1023
                int row = idx >> 3;
                int c8 = (idx & 7) * 8;
                int grow = row0 + row;
                if (grow >= NNODES) grow = NNODES - 1;   // clamp (x is exactly sized)
                const float* gp = pa + (size_t)grow * lda + c8;
                float4 u0 = *(const float4*)gp;
                float4 u1 = *(const float4*)(gp + 4);
                float f[8] = {u0.x, u0.y, u0.z, u0.w, u1.x, u1.y, u1.z, u1.w};
                float lo[8];
#pragma unroll
                for (int j = 0; j < 8; j++) {
                    __half h = __float2half_rn(f[j]);
                    lo[j] = f[j] - __half2float(h);
                }
                uint4 vh, vl;
                vh.x = pack2h(f[0], f[1]); vh.y = pack2h(f[2], f[3]);
                vh.z = pack2h(f[4], f[5]); vh.w = pack2h(f[6], f[7]);
                vl.x = pack2h(lo[0], lo[1]); vl.y = pack2h(lo[2], lo[3]);
                vl.z = pack2h(lo[4], lo[5]); vl.w = pack2h(lo[6], lo[7]);
                *(uint4*)&sAh[row * LDH + c8] = vh;
                *(uint4*)&sAl[row * LDH + c8] = vl;
            }
        }
        // stage W hi/lo transposed [n][k]
        {
            const float* Wc = W + sg * 4096;
            for (int i = tid; i < 4096; i += 256) {
                int k = i >> 6, n = i & 63;
                float w = Wc[i];
                __half hh = __float2half_rn(w);
                sWh[n * LDH + k] = hh;
                sWl[n * LDH + k] = __float2half_rn(w - __half2float(hh));
            }
        }
        __syncthreads();
#pragma unroll
        for (int kc = 0; kc < 64; kc += 16) {
            uint32_t ah[2][4], al[2][4];
#pragma unroll
            for (int mi = 0; mi < 2; mi++) {
                uint32_t aa = sb + OFF_AH + ((arow + mi * 16) * LDH + kc + acol) * 2;
                LDSM4(ah[mi], aa);
                LDSM4(al[mi], aa + (OFF_AL - OFF_AH));
            }
#pragma unroll
            for (int ni = 0; ni < 4; ni++) {
                uint32_t wh[2], wl[2];
                uint32_t ba = sb + OFF_WH + ((brow + ni * 8) * LDH + kc + bcol) * 2;
                LDSM2(wh, ba);
                LDSM2(wl, ba + (OFF_WL - OFF_WH));
#pragma unroll
                for (int mi = 0; mi < 2; mi++) {
                    MMA(acc[mi][ni], ah[mi], wh);
                    MMA(acc[mi][ni], al[mi], wh);
                    MMA(acc[mi][ni], ah[mi], wl);
                }
            }
        }
    }

    // ---- epilogue: park raw acc in smem (reuses A staging) ----
    __syncthreads();
    float* sC = (float*)(smem + OFF_CT);
    {
        int g = lane >> 2, qp = (lane & 3) * 2;
#pragma unroll
        for (int mi = 0; mi < 2; mi++)
#pragma unroll
            for (int ni = 0; ni < 4; ni++) {
                int r = wy * 32 + mi * 16 + g;
                int c = wx * 32 + ni * 8 + qp;
                *(float2*)&sC[r * LDF + c]       = make_float2(acc[mi][ni][0], acc[mi][ni][1]);
                *(float2*)&sC[(r + 8) * LDF + c] = make_float2(acc[mi][ni][2], acc[mi][ni][3]);
            }
    }
    __syncthreads();

    if (MODE != 2) {
#pragma unroll
        for (int it = 0; it < 4; it++) {
            int idx = tid + it * 256;
            int row = idx >> 3;
            int c8 = (idx & 7) * 8;
            float v[8];
#pragma unroll
            for (int j = 0; j < 8; j++)
                v[j] = fmaxf(sC[row * LDF + c8 + j] + sbias[c8 + j], 0.f);
            size_t base = (size_t)(row0 + row) * 64 + c8;
            *(float4*)(C + base)     = make_float4(v[0], v[1], v[2], v[3]);
            *(float4*)(C + base + 4) = make_float4(v[4], v[5], v[6], v[7]);
            if (MODE == 1) {
                float dn = g_dinv[row0 + row];
                uint4 ps;
                ps.x = pack2h(v[0] * dn, v[1] * dn); ps.y = pack2h(v[2] * dn, v[3] * dn);
                ps.z = pack2h(v[4] * dn, v[5] * dn); ps.w = pack2h(v[6] * dn, v[7] * dn);
                *(uint4*)(Cs + base) = ps;
            }
        }
    } else {
        int r = tid >> 1, c2 = tid & 1;
        float s = 0.f;
#pragma unroll
        for (int c = 0; c < 64; c++)
            s = fmaf(fmaxf(sC[r * LDF + c] + sbias[c], 0.f), swm2[c * 2 + c2], s);
        if (row0 + r < NNODES)
            out[(size_t)(row0 + r) * 2 + c2] = s + __ldg(&bm2[c2]);
    }
}

// ---------------- propagation (fp16 gather, fp32 diagonal) ----------------
// fout = fin - dinv[n] * sum_{s in in(n)} fins[s]
template <bool OUT_SCALED>
__global__ void __launch_bounds__(256) k_prop(
    const float* __restrict__ fin, const __half* __restrict__ fins,
    float* __restrict__ fout, __half* __restrict__ fouts)
{
    int n = (blockIdx.x * blockDim.x + threadIdx.x) >> 5;
    int lane = threadIdx.x & 31;
    int start = g_rowptr[n];
    int end = g_rowptr[n + 1];

    float ax = 0.f, ay = 0.f;
    for (int i = start; i < end; i += 32) {
        int cnt = min(32, end - i);
        int s = 0;
        if (lane < cnt) s = g_csrc[i + lane];
        int j = 0;
        for (; j + 4 <= cnt; j += 4) {
            int s0 = __shfl_sync(0xffffffffu, s, j);
            int s1 = __shfl_sync(0xffffffffu, s, j + 1);
            int s2 = __shfl_sync(0xffffffffu, s, j + 2);
            int s3 = __shfl_sync(0xffffffffu, s, j + 3);
            float2 v0 = __half22float2(*(const __half2*)&fins[(size_t)s0 * 64 + lane * 2]);
            float2 v1 = __half22float2(*(const __half2*)&fins[(size_t)s1 * 64 + lane * 2]);
            float2 v2 = __half22float2(*(const __half2*)&fins[(size_t)s2 * 64 + lane * 2]);
            float2 v3 = __half22float2(*(const __half2*)&fins[(size_t)s3 * 64 + lane * 2]);
            ax += (v0.x + v1.x) + (v2.x + v3.x);
            ay += (v0.y + v1.y) + (v2.y + v3.y);
        }
        for (; j < cnt; j++) {
            int sj = __shfl_sync(0xffffffffu, s, j);
            float2 v = __half22float2(*(const __half2*)&fins[(size_t)sj * 64 + lane * 2]);
            ax += v.x;
            ay += v.y;
        }
    }
    float dn = g_dinv[n];
    size_t base = (size_t)n * 64 + lane * 2;
    float2 cur = *(const float2*)&fin[base];
    float ox = cur.x - ax * dn;
    float oy = cur.y - ay * dn;
    *(float2*)&fout[base] = make_float2(ox, oy);
    if (OUT_SCALED)
        *(uint32_t*)&fouts[base] = pack2h(ox * dn, oy * dn);
}

// ---------------- launch ----------------
extern "C" void kernel_launch(void* const* d_in, const int* in_sizes, int n_in,
                              void* d_out, int out_size)
{
    const float* x   = (const float*)d_in[0];
    const void*  ei  = d_in[1];
    const float* W1  = (const float*)d_in[2];
    const float* b1  = (const float*)d_in[3];
    const float* W2  = (const float*)d_in[4];
    const float* b2  = (const float*)d_in[5];
    const float* Wm1 = (const float*)d_in[6];
    const float* bm1 = (const float*)d_in[7];
    const float* Wm2 = (const float*)d_in[8];
    const float* bm2 = (const float*)d_in[9];
    float* out = (float*)d_out;

    float *h1, *f0, *f1, *f2, *pwf, *pdinv;
    __half *f0s, *f1s;
    int *pdeg, *pflag;
    cudaGetSymbolAddress((void**)&h1, g_h1);
    cudaGetSymbolAddress((void**)&f0, g_f0);
    cudaGetSymbolAddress((void**)&f1, g_f1);
    cudaGetSymbolAddress((void**)&f2, g_f2);
    cudaGetSymbolAddress((void**)&f0s, g_f0s);
    cudaGetSymbolAddress((void**)&f1s, g_f1s);
    cudaGetSymbolAddress((void**)&pwf, g_wfold);
    cudaGetSymbolAddress((void**)&pdinv, g_dinv);
    cudaGetSymbolAddress((void**)&pdeg, g_deg);
    cudaGetSymbolAddress((void**)&pflag, g_flag);

    cudaFuncSetAttribute(k_mma<2, 0>, cudaFuncAttributeMaxDynamicSharedMemorySize, SMEM_SZ);
    cudaFuncSetAttribute(k_mma<1, 1>, cudaFuncAttributeMaxDynamicSharedMemorySize, SMEM_SZ);
    cudaFuncSetAttribute(k_mma<3, 2>, cudaFuncAttributeMaxDynamicSharedMemorySize, SMEM_SZ);

    // graph prep
    cudaMemsetAsync(pdeg, 0, NNODES * sizeof(int));
    cudaMemsetAsync(pflag, 0, sizeof(int));
    k_detect<<<256, 256>>>((const int*)ei);
    k_degree<<<NEDGES / 256, 256>>>(ei);
    k_blocksum<<<NBLK, SCAN_B>>>();
    k_scan_bsums<<<1, 512>>>();
    k_rowptr<<<NBLK, SCAN_B>>>();
    k_fill<<<NEDGES / 256, 256>>>(ei);
    k_fold<<<(3 * 64 * 64 + 255) / 256, 256>>>(Wm1);

    // h1 = relu(x @ W1 + b1)   (K=128: 2 segments)
    k_mma<2, 0><<<NTILES, 256, SMEM_SZ>>>(x, x + 64, nullptr, 128, W1, b1,
                                          h1, nullptr, nullptr, nullptr, nullptr);
    // f0 = relu(h1 @ W2 + b2), f0s = f0 * dinv
    k_mma<1, 1><<<NTILES, 256, SMEM_SZ>>>(h1, nullptr, nullptr, 64, W2, b2,
                                          f0, f0s, nullptr, nullptr, nullptr);
    // f1 = P f0, f2 = P f1
    k_prop<true><<<(NNODES * 32) / 256, 256>>>(f0, f0s, f1, f1s);
    k_prop<false><<<(NNODES * 32) / 256, 256>>>(f1, f1s, f2, nullptr);

    // head: out = relu(f0@Wf0 + f1@Wf1 + f2@Wf2 + bm1) @ Wm2 + bm2
    k_mma<3, 2><<<NTILES, 256, SMEM_SZ>>>(f0, f1, f2, 64, pwf, bm1,
                                          nullptr, nullptr, Wm2, bm2, out);
}

// round 6
// speedup vs baseline: 2.9168x; 1.0635x over previous
#include <cuda_runtime.h>
#include <cuda_fp16.h>
#include <cstdint>

#define NNODES 100000
#define NEDGES 1600000
#define NPAD   100096          // 782 * 128
#define NTILES 782
#define SCAN_B 256
#define NBLK ((NNODES + SCAN_B - 1) / SCAN_B)   // 391

// ---------------- static device scratch ----------------
__device__ float  g_h1[NPAD * 64];
__device__ float  g_f0[NPAD * 64], g_f1[NPAD * 64], g_f2[NPAD * 64];
__device__ __half g_f0s[NPAD * 64], g_f1s[NPAD * 64];
__device__ int    g_csrc[NEDGES];
__device__ int    g_deg[NNODES], g_rowptr[NNODES + 1], g_cursor[NNODES], g_bsum[NBLK];
__device__ float  g_dinv[NPAD];            // tail stays zero
__device__ float  g_wfold[3 * 64 * 64];
__device__ int    g_flag;                  // 0 = int64 edges, 1 = int32

// ---------------- helpers ----------------
__device__ __forceinline__ uint32_t smem_u32(const void* p) {
    uint32_t a;
    asm("{ .reg .u64 t; cvta.to.shared.u64 t, %1; cvt.u32.u64 %0, t; }" : "=r"(a) : "l"(p));
    return a;
}
__device__ __forceinline__ uint32_t pack2h(float a, float b) {
    __half2 h = __floats2half2_rn(a, b);
    return *reinterpret_cast<uint32_t*>(&h);
}

#define LDSM4(d, a)                                                              \
    asm volatile("ldmatrix.sync.aligned.m8n8.x4.shared.b16 {%0,%1,%2,%3}, [%4];" \
                 : "=r"((d)[0]), "=r"((d)[1]), "=r"((d)[2]), "=r"((d)[3]) : "r"(a))
#define LDSM2(d, a)                                                              \
    asm volatile("ldmatrix.sync.aligned.m8n8.x2.shared.b16 {%0,%1}, [%2];"       \
                 : "=r"((d)[0]), "=r"((d)[1]) : "r"(a))
#define MMA(c, a, b)                                                             \
    asm volatile("mma.sync.aligned.m16n8k16.row.col.f32.f16.f16.f32 "            \
                 "{%0,%1,%2,%3},{%4,%5,%6,%7},{%8,%9},{%0,%1,%2,%3};"            \
                 : "+f"((c)[0]), "+f"((c)[1]), "+f"((c)[2]), "+f"((c)[3])        \
                 : "r"((a)[0]), "r"((a)[1]), "r"((a)[2]), "r"((a)[3]),           \
                   "r"((b)[0]), "r"((b)[1]))

// ---------------- prep kernels ----------------
__global__ void k_detect(const int* __restrict__ e32) {
    int i = blockIdx.x * blockDim.x + threadIdx.x;
    int stride = gridDim.x * blockDim.x;
    for (int e = i; e < NEDGES; e += stride)
        if (e32[2 * e + 1] != 0) { g_flag = 1; break; }
}
__global__ void k_degree(const void* __restrict__ eptr) {
    int e = blockIdx.x * blockDim.x + threadIdx.x;
    if (e >= NEDGES) return;
    int d;
    if (g_flag == 0) d = (int)((const long long*)eptr)[NEDGES + e];
    else             d = ((const int*)eptr)[NEDGES + e];
    atomicAdd(&g_deg[d], 1);
}
__global__ void k_blocksum() {
    __shared__ int sh[SCAN_B];
    int i = blockIdx.x * SCAN_B + threadIdx.x;
    sh[threadIdx.x] = (i < NNODES) ? g_deg[i] : 0;
    __syncthreads();
    for (int off = SCAN_B / 2; off > 0; off >>= 1) {
        if (threadIdx.x < off) sh[threadIdx.x] += sh[threadIdx.x + off];
        __syncthreads();
    }
    if (threadIdx.x == 0) g_bsum[blockIdx.x] = sh[0];
}
__global__ void k_scan_bsums() {
    __shared__ int sh[512];
    int t = threadIdx.x;
    sh[t] = (t < NBLK) ? g_bsum[t] : 0;
    __syncthreads();
    for (int off = 1; off < 512; off <<= 1) {
        int v = (t >= off) ? sh[t - off] : 0;
        __syncthreads();
        sh[t] += v;
        __syncthreads();
    }
    if (t < NBLK) g_bsum[t] = sh[t];
}
__global__ void k_rowptr() {
    __shared__ int sh[SCAN_B];
    int b = blockIdx.x;
    int i = b * SCAN_B + threadIdx.x;
    int d = (i < NNODES) ? g_deg[i] : 0;
    sh[threadIdx.x] = d;
    __syncthreads();
    for (int off = 1; off < SCAN_B; off <<= 1) {
        int v = (threadIdx.x >= off) ? sh[threadIdx.x - off] : 0;
        __syncthreads();
        sh[threadIdx.x] += v;
        __syncthreads();
    }
    int incl = sh[threadIdx.x];
    int boff = (b == 0) ? 0 : g_bsum[b - 1];
    if (i < NNODES) {
        int r = boff + incl - d;
        g_rowptr[i] = r;
        g_cursor[i] = r;
        g_dinv[i] = rsqrtf((float)(d > 0 ? d : 1));
        if (i == NNODES - 1) g_rowptr[NNODES] = boff + incl;
    }
}
__global__ void k_fill(const void* __restrict__ eptr) {
    int e = blockIdx.x * blockDim.x + threadIdx.x;
    if (e >= NEDGES) return;
    int s, d;
    if (g_flag == 0) {
        const long long* p = (const long long*)eptr;
        s = (int)p[e]; d = (int)p[NEDGES + e];
    } else {
        const int* p = (const int*)eptr;
        s = p[e]; d = p[NEDGES + e];
    }
    int pos = atomicAdd(&g_cursor[d], 1);
    g_csrc[pos] = s;
}
// fold thetas: t0=[3,-3,0.75], t1=[0,3,-1.5], t2=[0,0,0.75]
__global__ void k_fold(const float* __restrict__ Wm1) {
    int idx = blockIdx.x * blockDim.x + threadIdx.x;
    if (idx >= 3 * 64 * 64) return;
    int k = idx >> 12, ij = idx & 4095;
    float c0, c1, c2;
    if (k == 0)      { c0 = 3.0f;  c1 = 0.0f;  c2 = 0.0f;  }
    else if (k == 1) { c0 = -3.0f; c1 = 3.0f;  c2 = 0.0f;  }
    else             { c0 = 0.75f; c1 = -1.5f; c2 = 0.75f; }
    g_wfold[idx] = c0 * Wm1[ij] + c1 * Wm1[4096 + ij] + c2 * Wm1[2 * 4096 + ij];
}
// f0s = f0 * dinv (rowwise), fp16
__global__ void k_scale(const float* __restrict__ f, __half* __restrict__ fs) {
    int idx = blockIdx.x * blockDim.x + threadIdx.x;   // one thread per 2 elems
    int row = idx >> 5;
    int c2 = idx & 31;
    float dn = g_dinv[row];
    float2 v = *(const float2*)&f[(size_t)row * 64 + c2 * 2];
    *(uint32_t*)&fs[(size_t)row * 64 + c2 * 2] = pack2h(v.x * dn, v.y * dn);
}

// ---------------- HMMA GEMM ----------------
// C[128x64] = act( sum_seg A_seg[128x64](fp32) @ W_seg[64x64](fp32) + bias )
// fp16 hi/lo split in staging registers, fp32 accumulate via mma.sync.
// MODE 0: write fp32 C. MODE 2: fused @Wm2+bm2 head.
#define LDH 72
#define LDF 68
#define OFF_BIAS 0
#define OFF_WM2  256
#define OFF_CT   768
#define OFF_AH   768
#define OFF_AL   (OFF_AH + 128 * LDH * 2)
#define OFF_WH   (OFF_AL + 128 * LDH * 2)
#define OFF_WL   (OFF_WH + 64 * LDH * 2)
#define SMEM_SZ  (OFF_WL + 64 * LDH * 2)

template <int NSEG, int MODE>
__global__ void __launch_bounds__(256) k_mma(
    const float* __restrict__ A0, const float* __restrict__ A1, const float* __restrict__ A2,
    int lda,
    const float* __restrict__ W, const float* __restrict__ bias,
    float* __restrict__ C,
    const float* __restrict__ Wm2, const float* __restrict__ bm2,
    float* __restrict__ out)
{
    extern __shared__ char smem[];
    uint32_t sb = smem_u32(smem);
    float* sbias = (float*)(smem + OFF_BIAS);
    float* swm2  = (float*)(smem + OFF_WM2);
    __half* sAh = (__half*)(smem + OFF_AH);
    __half* sAl = (__half*)(smem + OFF_AL);
    __half* sWh = (__half*)(smem + OFF_WH);
    __half* sWl = (__half*)(smem + OFF_WL);

    int tid = threadIdx.x;
    int warp = tid >> 5, lane = tid & 31;
    int wy = warp & 3, wx = warp >> 2;
    int row0 = blockIdx.x * 128;

    if (tid < 64) sbias[tid] = bias[tid];
    if (MODE == 2 && tid < 128) swm2[tid] = Wm2[tid];

    float acc[2][4][4];
#pragma unroll
    for (int mi = 0; mi < 2; mi++)
#pragma unroll
        for (int ni = 0; ni < 4; ni++)
#pragma unroll
            for (int j = 0; j < 4; j++) acc[mi][ni][j] = 0.f;

    const float* Aseg[3] = {A0, A1, A2};

    const int arow = wy * 32 + (lane & 7) + ((lane >> 3) & 1) * 8;
    const int acol = ((lane >> 4) & 1) * 8;
    const int brow = wx * 32 + (lane & 7);
    const int bcol = ((lane >> 3) & 1) * 8;

#pragma unroll
    for (int sg = 0; sg < NSEG; sg++) {
        __syncthreads();
        {
            const float* pa = Aseg[sg];
#pragma unroll
            for (int it = 0; it < 4; it++) {
                int idx = tid + it * 256;
                int row = idx >> 3;
                int c8 = (idx & 7) * 8;
                int grow = row0 + row;
                if (grow >= NNODES) grow = NNODES - 1;
                const float* gp = pa + (size_t)grow * lda + c8;
                float4 u0 = *(const float4*)gp;
                float4 u1 = *(const float4*)(gp + 4);
                float f[8] = {u0.x, u0.y, u0.z, u0.w, u1.x, u1.y, u1.z, u1.w};
                float lo[8];
#pragma unroll
                for (int j = 0; j < 8; j++) {
                    __half h = __float2half_rn(f[j]);
                    lo[j] = f[j] - __half2float(h);
                }
                uint4 vh, vl;
                vh.x = pack2h(f[0], f[1]); vh.y = pack2h(f[2], f[3]);
                vh.z = pack2h(f[4], f[5]); vh.w = pack2h(f[6], f[7]);
                vl.x = pack2h(lo[0], lo[1]); vl.y = pack2h(lo[2], lo[3]);
                vl.z = pack2h(lo[4], lo[5]); vl.w = pack2h(lo[6], lo[7]);
                *(uint4*)&sAh[row * LDH + c8] = vh;
                *(uint4*)&sAl[row * LDH + c8] = vl;
            }
        }
        {
            const float* Wc = W + sg * 4096;
            for (int i = tid; i < 4096; i += 256) {
                int k = i >> 6, n = i & 63;
                float w = Wc[i];
                __half hh = __float2half_rn(w);
                sWh[n * LDH + k] = hh;
                sWl[n * LDH + k] = __float2half_rn(w - __half2float(hh));
            }
        }
        __syncthreads();
#pragma unroll
        for (int kc = 0; kc < 64; kc += 16) {
            uint32_t ah[2][4], al[2][4];
#pragma unroll
            for (int mi = 0; mi < 2; mi++) {
                uint32_t aa = sb + OFF_AH + ((arow + mi * 16) * LDH + kc + acol) * 2;
                LDSM4(ah[mi], aa);
                LDSM4(al[mi], aa + (OFF_AL - OFF_AH));
            }
#pragma unroll
            for (int ni = 0; ni < 4; ni++) {
                uint32_t wh[2], wl[2];
                uint32_t ba = sb + OFF_WH + ((brow + ni * 8) * LDH + kc + bcol) * 2;
                LDSM2(wh, ba);
                LDSM2(wl, ba + (OFF_WL - OFF_WH));
#pragma unroll
                for (int mi = 0; mi < 2; mi++) {
                    MMA(acc[mi][ni], ah[mi], wh);
                    MMA(acc[mi][ni], al[mi], wh);
                    MMA(acc[mi][ni], ah[mi], wl);
                }
            }
        }
    }

    __syncthreads();
    float* sC = (float*)(smem + OFF_CT);
    {
        int g = lane >> 2, qp = (lane & 3) * 2;
#pragma unroll
        for (int mi = 0; mi < 2; mi++)
#pragma unroll
            for (int ni = 0; ni < 4; ni++) {
                int r = wy * 32 + mi * 16 + g;
                int c = wx * 32 + ni * 8 + qp;
                *(float2*)&sC[r * LDF + c]       = make_float2(acc[mi][ni][0], acc[mi][ni][1]);
                *(float2*)&sC[(r + 8) * LDF + c] = make_float2(acc[mi][ni][2], acc[mi][ni][3]);
            }
    }
    __syncthreads();

    if (MODE != 2) {
#pragma unroll
        for (int it = 0; it < 4; it++) {
            int idx = tid + it * 256;
            int row = idx >> 3;
            int c8 = (idx & 7) * 8;
            float v[8];
#pragma unroll
            for (int j = 0; j < 8; j++)
                v[j] = fmaxf(sC[row * LDF + c8 + j] + sbias[c8 + j], 0.f);
            size_t base = (size_t)(row0 + row) * 64 + c8;
            *(float4*)(C + base)     = make_float4(v[0], v[1], v[2], v[3]);
            *(float4*)(C + base + 4) = make_float4(v[4], v[5], v[6], v[7]);
        }
    } else {
        int r = tid >> 1, c2 = tid & 1;
        float s = 0.f;
#pragma unroll
        for (int c = 0; c < 64; c++)
            s = fmaf(fmaxf(sC[r * LDF + c] + sbias[c], 0.f), swm2[c * 2 + c2], s);
        if (row0 + r < NNODES)
            out[(size_t)(row0 + r) * 2 + c2] = s + __ldg(&bm2[c2]);
    }
}

// ---------------- propagation (fp16 gather, fp32 diagonal) ----------------
template <bool OUT_SCALED>
__global__ void __launch_bounds__(256) k_prop(
    const float* __restrict__ fin, const __half* __restrict__ fins,
    float* __restrict__ fout, __half* __restrict__ fouts)
{
    int n = (blockIdx.x * blockDim.x + threadIdx.x) >> 5;
    int lane = threadIdx.x & 31;
    int start = g_rowptr[n];
    int end = g_rowptr[n + 1];

    float ax = 0.f, ay = 0.f;
    for (int i = start; i < end; i += 32) {
        int cnt = min(32, end - i);
        int s = 0;
        if (lane < cnt) s = g_csrc[i + lane];
        int j = 0;
        for (; j + 4 <= cnt; j += 4) {
            int s0 = __shfl_sync(0xffffffffu, s, j);
            int s1 = __shfl_sync(0xffffffffu, s, j + 1);
            int s2 = __shfl_sync(0xffffffffu, s, j + 2);
            int s3 = __shfl_sync(0xffffffffu, s, j + 3);
            float2 v0 = __half22float2(*(const __half2*)&fins[(size_t)s0 * 64 + lane * 2]);
            float2 v1 = __half22float2(*(const __half2*)&fins[(size_t)s1 * 64 + lane * 2]);
            float2 v2 = __half22float2(*(const __half2*)&fins[(size_t)s2 * 64 + lane * 2]);
            float2 v3 = __half22float2(*(const __half2*)&fins[(size_t)s3 * 64 + lane * 2]);
            ax += (v0.x + v1.x) + (v2.x + v3.x);
            ay += (v0.y + v1.y) + (v2.y + v3.y);
        }
        for (; j < cnt; j++) {
            int sj = __shfl_sync(0xffffffffu, s, j);
            float2 v = __half22float2(*(const __half2*)&fins[(size_t)sj * 64 + lane * 2]);
            ax += v.x;
            ay += v.y;
        }
    }
    float dn = g_dinv[n];
    size_t base = (size_t)n * 64 + lane * 2;
    float2 cur = *(const float2*)&fin[base];
    float ox = cur.x - ax * dn;
    float oy = cur.y - ay * dn;
    *(float2*)&fout[base] = make_float2(ox, oy);
    if (OUT_SCALED)
        *(uint32_t*)&fouts[base] = pack2h(ox * dn, oy * dn);
}

// ---------------- launch ----------------
extern "C" void kernel_launch(void* const* d_in, const int* in_sizes, int n_in,
                              void* d_out, int out_size)
{
    const float* x   = (const float*)d_in[0];
    const void*  ei  = d_in[1];
    const float* W1  = (const float*)d_in[2];
    const float* b1  = (const float*)d_in[3];
    const float* W2  = (const float*)d_in[4];
    const float* b2  = (const float*)d_in[5];
    const float* Wm1 = (const float*)d_in[6];
    const float* bm1 = (const float*)d_in[7];
    const float* Wm2 = (const float*)d_in[8];
    const float* bm2 = (const float*)d_in[9];
    float* out = (float*)d_out;

    float *h1, *f0, *f1, *f2, *pwf;
    __half *f0s, *f1s;
    int *pdeg, *pflag;
    cudaGetSymbolAddress((void**)&h1, g_h1);
    cudaGetSymbolAddress((void**)&f0, g_f0);
    cudaGetSymbolAddress((void**)&f1, g_f1);
    cudaGetSymbolAddress((void**)&f2, g_f2);
    cudaGetSymbolAddress((void**)&f0s, g_f0s);
    cudaGetSymbolAddress((void**)&f1s, g_f1s);
    cudaGetSymbolAddress((void**)&pwf, g_wfold);
    cudaGetSymbolAddress((void**)&pdeg, g_deg);
    cudaGetSymbolAddress((void**)&pflag, g_flag);

    cudaFuncSetAttribute(k_mma<2, 0>, cudaFuncAttributeMaxDynamicSharedMemorySize, SMEM_SZ);
    cudaFuncSetAttribute(k_mma<1, 0>, cudaFuncAttributeMaxDynamicSharedMemorySize, SMEM_SZ);
    cudaFuncSetAttribute(k_mma<3, 2>, cudaFuncAttributeMaxDynamicSharedMemorySize, SMEM_SZ);

    // fork/join resources (created once; handles only, no device memory)
    static cudaStream_t s_side = [] {
        cudaStream_t s;
        return (cudaStreamCreateWithFlags(&s, cudaStreamNonBlocking) == cudaSuccess)
                   ? s : (cudaStream_t)nullptr;
    }();
    static cudaEvent_t e_fork = [] {
        cudaEvent_t e;
        return (cudaEventCreateWithFlags(&e, cudaEventDisableTiming) == cudaSuccess)
                   ? e : (cudaEvent_t)nullptr;
    }();
    static cudaEvent_t e_join = [] {
        cudaEvent_t e;
        return (cudaEventCreateWithFlags(&e, cudaEventDisableTiming) == cudaSuccess)
                   ? e : (cudaEvent_t)nullptr;
    }();

    bool overlap = (s_side != nullptr) && (e_fork != nullptr) && (e_join != nullptr);
    cudaStream_t sp = overlap ? s_side : (cudaStream_t)0;   // prep stream

    if (overlap) {
        cudaEventRecord(e_fork, 0);
        cudaStreamWaitEvent(s_side, e_fork, 0);
    }

    // ---- prep chain (side stream when overlapping) ----
    cudaMemsetAsync(pdeg, 0, NNODES * sizeof(int), sp);
    cudaMemsetAsync(pflag, 0, sizeof(int), sp);
    k_detect<<<256, 256, 0, sp>>>((const int*)ei);
    k_degree<<<NEDGES / 256, 256, 0, sp>>>(ei);
    k_blocksum<<<NBLK, SCAN_B, 0, sp>>>();
    k_scan_bsums<<<1, 512, 0, sp>>>();
    k_rowptr<<<NBLK, SCAN_B, 0, sp>>>();
    k_fill<<<NEDGES / 256, 256, 0, sp>>>(ei);
    if (overlap) cudaEventRecord(e_join, s_side);

    // ---- MLP chain (main stream; independent of graph) ----
    k_fold<<<(3 * 64 * 64 + 255) / 256, 256>>>(Wm1);
    k_mma<2, 0><<<NTILES, 256, SMEM_SZ>>>(x, x + 64, nullptr, 128, W1, b1,
                                          h1, nullptr, nullptr, nullptr);
    k_mma<1, 0><<<NTILES, 256, SMEM_SZ>>>(h1, nullptr, nullptr, 64, W2, b2,
                                          f0, nullptr, nullptr, nullptr);

    // ---- join ----
    if (overlap) cudaStreamWaitEvent(0, e_join, 0);

    // f0s = f0 * dinv
    k_scale<<<(NNODES * 32) / 256, 256>>>(f0, f0s);
    // f1 = P f0, f2 = P f1
    k_prop<true><<<(NNODES * 32) / 256, 256>>>(f0, f0s, f1, f1s);
    k_prop<false><<<(NNODES * 32) / 256, 256>>>(f1, f1s, f2, nullptr);

    // head: out = relu(f0@Wf0 + f1@Wf1 + f2@Wf2 + bm1) @ Wm2 + bm2
    k_mma<3, 2><<<NTILES, 256, SMEM_SZ>>>(f0, f1, f2, 64, pwf, bm1,
                                          nullptr, Wm2, bm2, out);
}

// round 7
// speedup vs baseline: 2.9393x; 1.0077x over previous
#include <cuda_runtime.h>
#include <cuda_fp16.h>
#include <cstdint>

#define NNODES 100000
#define NEDGES 1600000
#define NPAD   100096          // 782 * 128
#define NTILES 782
#define SCAN_B 256
#define NBLK ((NNODES + SCAN_B - 1) / SCAN_B)   // 391

// ---------------- static device scratch ----------------
__device__ float  g_h1[NPAD * 64];
__device__ float  g_f0[NPAD * 64], g_f1[NPAD * 64], g_f2[NPAD * 64];
__device__ __half g_f0s[NPAD * 64], g_f1s[NPAD * 64];
__device__ int    g_csrc[NEDGES];
__device__ int    g_deg[NNODES], g_rowptr[NNODES + 1], g_cursor[NNODES];
__device__ unsigned long long g_pstate[NBLK];   // decoupled-lookback state
__device__ float  g_dinv[NPAD];                 // tail stays zero
__device__ float  g_wfold[3 * 64 * 64];
__device__ int    g_flag;                       // 0 = int64 edges, 1 = int32

// ---------------- helpers ----------------
__device__ __forceinline__ uint32_t smem_u32(const void* p) {
    uint32_t a;
    asm("{ .reg .u64 t; cvta.to.shared.u64 t, %1; cvt.u32.u64 %0, t; }" : "=r"(a) : "l"(p));
    return a;
}
__device__ __forceinline__ uint32_t pack2h(float a, float b) {
    __half2 h = __floats2half2_rn(a, b);
    return *reinterpret_cast<uint32_t*>(&h);
}
__device__ __forceinline__ unsigned long long ldv64(const unsigned long long* p) {
    unsigned long long v;
    asm volatile("ld.volatile.global.u64 %0, [%1];" : "=l"(v) : "l"(p));
    return v;
}

#define LDSM4(d, a)                                                              \
    asm volatile("ldmatrix.sync.aligned.m8n8.x4.shared.b16 {%0,%1,%2,%3}, [%4];" \
                 : "=r"((d)[0]), "=r"((d)[1]), "=r"((d)[2]), "=r"((d)[3]) : "r"(a))
#define LDSM2(d, a)                                                              \
    asm volatile("ldmatrix.sync.aligned.m8n8.x2.shared.b16 {%0,%1}, [%2];"       \
                 : "=r"((d)[0]), "=r"((d)[1]) : "r"(a))
#define MMA(c, a, b)                                                             \
    asm volatile("mma.sync.aligned.m16n8k16.row.col.f32.f16.f16.f32 "            \
                 "{%0,%1,%2,%3},{%4,%5,%6,%7},{%8,%9},{%0,%1,%2,%3};"            \
                 : "+f"((c)[0]), "+f"((c)[1]), "+f"((c)[2]), "+f"((c)[3])        \
                 : "r"((a)[0]), "r"((a)[1]), "r"((a)[2]), "r"((a)[3]),           \
                   "r"((b)[0]), "r"((b)[1]))

// ---------------- prep kernels ----------------
// sampled dtype probe: int64 node ids < 2^31 have zero high words; for int32
// data the odds that 2048 consecutive odd-position ids are all zero are nil.
__global__ void k_detect(const int* __restrict__ e32) {
    int nz = 0;
    for (int e = threadIdx.x; e < 2048; e += 256) nz |= e32[2 * e + 1];
    if (__syncthreads_or(nz) && threadIdx.x == 0) g_flag = 1;
}
__global__ void k_degree(const void* __restrict__ eptr) {
    int e = blockIdx.x * blockDim.x + threadIdx.x;
    if (e >= NEDGES) return;
    int d;
    if (g_flag == 0) d = (int)((const long long*)eptr)[NEDGES + e];
    else             d = ((const int*)eptr)[NEDGES + e];
    atomicAdd(&g_deg[d], 1);
}

// single-pass scan: block-local Hillis-Steele + decoupled lookback.
// g_pstate[b] = (flag<<32)|value; flag 1 = aggregate, 2 = inclusive prefix.
__global__ void k_scan_fused() {
    __shared__ int sh[SCAN_B];
    __shared__ int s_base;
    int b = blockIdx.x, t = threadIdx.x;
    int i = b * SCAN_B + t;
    int d = (i < NNODES) ? g_deg[i] : 0;
    sh[t] = d;
    __syncthreads();
    for (int off = 1; off < SCAN_B; off <<= 1) {
        int v = (t >= off) ? sh[t - off] : 0;
        __syncthreads();
        sh[t] += v;
        __syncthreads();
    }
    int incl = sh[t];
    int agg = sh[SCAN_B - 1];
    if (t == 0) {
        if (b == 0) {
            s_base = 0;
            atomicExch(&g_pstate[0], (2ull << 32) | (unsigned)agg);
        } else {
            atomicExch(&g_pstate[b], (1ull << 32) | (unsigned)agg);
        }
    }
    if (b > 0 && t < 32) {
        int running = 0;
        int j = b - 1;
        for (;;) {
            int jj = j - t;
            unsigned long long st;
            unsigned f;
            do {
                st = (jj >= 0) ? ldv64(&g_pstate[jj]) : (2ull << 32);
                f = (unsigned)(st >> 32);
            } while (__ballot_sync(0xffffffffu, f == 0));
            int v = (jj >= 0) ? (int)(st & 0xffffffffu) : 0;
            unsigned pm = __ballot_sync(0xffffffffu, (jj >= 0) && (f == 2));
            if (pm) {
                int fl = __ffs(pm) - 1;          // lowest lane = largest jj with prefix
                if ((int)t > fl) v = 0;
#pragma unroll
                for (int o = 16; o; o >>= 1) v += __shfl_xor_sync(0xffffffffu, v, o);
                running += v;
                break;
            }
#pragma unroll
            for (int o = 16; o; o >>= 1) v += __shfl_xor_sync(0xffffffffu, v, o);
            running += v;
            j -= 32;
        }
        if (t == 0) {
            s_base = running;
            atomicExch(&g_pstate[b], (2ull << 32) | (unsigned)(running + agg));
        }
    }
    __syncthreads();
    int base = s_base;
    if (i < NNODES) {
        int r = base + incl - d;                 // exclusive prefix
        g_rowptr[i] = r;
        g_cursor[i] = r;
        g_dinv[i] = rsqrtf((float)(d > 0 ? d : 1));
        if (i == NNODES - 1) g_rowptr[NNODES] = base + incl;
    }
}

__global__ void k_fill(const void* __restrict__ eptr) {
    int e = blockIdx.x * blockDim.x + threadIdx.x;
    if (e >= NEDGES) return;
    int s, d;
    if (g_flag == 0) {
        const long long* p = (const long long*)eptr;
        s = (int)p[e]; d = (int)p[NEDGES + e];
    } else {
        const int* p = (const int*)eptr;
        s = p[e]; d = p[NEDGES + e];
    }
    int pos = atomicAdd(&g_cursor[d], 1);
    g_csrc[pos] = s;
}
// fold thetas: t0=[3,-3,0.75], t1=[0,3,-1.5], t2=[0,0,0.75]
__global__ void k_fold(const float* __restrict__ Wm1) {
    int idx = blockIdx.x * blockDim.x + threadIdx.x;
    if (idx >= 3 * 64 * 64) return;
    int k = idx >> 12, ij = idx & 4095;
    float c0, c1, c2;
    if (k == 0)      { c0 = 3.0f;  c1 = 0.0f;  c2 = 0.0f;  }
    else if (k == 1) { c0 = -3.0f; c1 = 3.0f;  c2 = 0.0f;  }
    else             { c0 = 0.75f; c1 = -1.5f; c2 = 0.75f; }
    g_wfold[idx] = c0 * Wm1[ij] + c1 * Wm1[4096 + ij] + c2 * Wm1[2 * 4096 + ij];
}

// ---------------- HMMA GEMM ----------------
// C[128x64] = act( sum_seg A_seg[128x64](fp32) @ W_seg[64x64](fp32) + bias )
// fp16 hi/lo split in staging registers, fp32 accumulate via mma.sync.
// MODE 0: fp32 C. MODE 1: fp32 C + fp16 prescaled Cs = C*dinv. MODE 2: fused @Wm2+bm2 head.
#define LDH 72
#define LDF 68
#define OFF_BIAS 0
#define OFF_WM2  256
#define OFF_CT   768
#define OFF_AH   768
#define OFF_AL   (OFF_AH + 128 * LDH * 2)
#define OFF_WH   (OFF_AL + 128 * LDH * 2)
#define OFF_WL   (OFF_WH + 64 * LDH * 2)
#define SMEM_SZ  (OFF_WL + 64 * LDH * 2)

template <int NSEG, int MODE>
__global__ void __launch_bounds__(256) k_mma(
    const float* __restrict__ A0, const float* __restrict__ A1, const float* __restrict__ A2,
    int lda,
    const float* __restrict__ W, const float* __restrict__ bias,
    float* __restrict__ C, __half* __restrict__ Cs,
    const float* __restrict__ Wm2, const float* __restrict__ bm2,
    float* __restrict__ out)
{
    extern __shared__ char smem[];
    uint32_t sb = smem_u32(smem);
    float* sbias = (float*)(smem + OFF_BIAS);
    float* swm2  = (float*)(smem + OFF_WM2);
    __half* sAh = (__half*)(smem + OFF_AH);
    __half* sAl = (__half*)(smem + OFF_AL);
    __half* sWh = (__half*)(smem + OFF_WH);
    __half* sWl = (__half*)(smem + OFF_WL);

    int tid = threadIdx.x;
    int warp = tid >> 5, lane = tid & 31;
    int wy = warp & 3, wx = warp >> 2;
    int row0 = blockIdx.x * 128;

    if (tid < 64) sbias[tid] = bias[tid];
    if (MODE == 2 && tid < 128) swm2[tid] = Wm2[tid];

    float acc[2][4][4];
#pragma unroll
    for (int mi = 0; mi < 2; mi++)
#pragma unroll
        for (int ni = 0; ni < 4; ni++)
#pragma unroll
            for (int j = 0; j < 4; j++) acc[mi][ni][j] = 0.f;

    const float* Aseg[3] = {A0, A1, A2};

    const int arow = wy * 32 + (lane & 7) + ((lane >> 3) & 1) * 8;
    const int acol = ((lane >> 4) & 1) * 8;
    const int brow = wx * 32 + (lane & 7);
    const int bcol = ((lane >> 3) & 1) * 8;

#pragma unroll
    for (int sg = 0; sg < NSEG; sg++) {
        __syncthreads();
        {
            const float* pa = Aseg[sg];
#pragma unroll
            for (int it = 0; it < 4; it++) {
                int idx = tid + it * 256;
                int row = idx >> 3;
                int c8 = (idx & 7) * 8;
                int grow = row0 + row;
                if (grow >= NNODES) grow = NNODES - 1;
                const float* gp = pa + (size_t)grow * lda + c8;
                float4 u0 = *(const float4*)gp;
                float4 u1 = *(const float4*)(gp + 4);
                float f[8] = {u0.x, u0.y, u0.z, u0.w, u1.x, u1.y, u1.z, u1.w};
                float lo[8];
#pragma unroll
                for (int j = 0; j < 8; j++) {
                    __half h = __float2half_rn(f[j]);
                    lo[j] = f[j] - __half2float(h);
                }
                uint4 vh, vl;
                vh.x = pack2h(f[0], f[1]); vh.y = pack2h(f[2], f[3]);
                vh.z = pack2h(f[4], f[5]); vh.w = pack2h(f[6], f[7]);
                vl.x = pack2h(lo[0], lo[1]); vl.y = pack2h(lo[2], lo[3]);
                vl.z = pack2h(lo[4], lo[5]); vl.w = pack2h(lo[6], lo[7]);
                *(uint4*)&sAh[row * LDH + c8] = vh;
                *(uint4*)&sAl[row * LDH + c8] = vl;
            }
        }
        {
            const float* Wc = W + sg * 4096;
            for (int i = tid; i < 4096; i += 256) {
                int k = i >> 6, n = i & 63;
                float w = Wc[i];
                __half hh = __float2half_rn(w);
                sWh[n * LDH + k] = hh;
                sWl[n * LDH + k] = __float2half_rn(w - __half2float(hh));
            }
        }
        __syncthreads();
#pragma unroll
        for (int kc = 0; kc < 64; kc += 16) {
            uint32_t ah[2][4], al[2][4];
#pragma unroll
            for (int mi = 0; mi < 2; mi++) {
                uint32_t aa = sb + OFF_AH + ((arow + mi * 16) * LDH + kc + acol) * 2;
                LDSM4(ah[mi], aa);
                LDSM4(al[mi], aa + (OFF_AL - OFF_AH));
            }
#pragma unroll
            for (int ni = 0; ni < 4; ni++) {
                uint32_t wh[2], wl[2];
                uint32_t ba = sb + OFF_WH + ((brow + ni * 8) * LDH + kc + bcol) * 2;
                LDSM2(wh, ba);
                LDSM2(wl, ba + (OFF_WL - OFF_WH));
#pragma unroll
                for (int mi = 0; mi < 2; mi++) {
                    MMA(acc[mi][ni], ah[mi], wh);
                    MMA(acc[mi][ni], al[mi], wh);
                    MMA(acc[mi][ni], ah[mi], wl);
                }
            }
        }
    }

    __syncthreads();
    float* sC = (float*)(smem + OFF_CT);
    {
        int g = lane >> 2, qp = (lane & 3) * 2;
#pragma unroll
        for (int mi = 0; mi < 2; mi++)
#pragma unroll
            for (int ni = 0; ni < 4; ni++) {
                int r = wy * 32 + mi * 16 + g;
                int c = wx * 32 + ni * 8 + qp;
                *(float2*)&sC[r * LDF + c]       = make_float2(acc[mi][ni][0], acc[mi][ni][1]);
                *(float2*)&sC[(r + 8) * LDF + c] = make_float2(acc[mi][ni][2], acc[mi][ni][3]);
            }
    }
    __syncthreads();

    if (MODE != 2) {
#pragma unroll
        for (int it = 0; it < 4; it++) {
            int idx = tid + it * 256;
            int row = idx >> 3;
            int c8 = (idx & 7) * 8;
            float v[8];
#pragma unroll
            for (int j = 0; j < 8; j++)
                v[j] = fmaxf(sC[row * LDF + c8 + j] + sbias[c8 + j], 0.f);
            size_t base = (size_t)(row0 + row) * 64 + c8;
            *(float4*)(C + base)     = make_float4(v[0], v[1], v[2], v[3]);
            *(float4*)(C + base + 4) = make_float4(v[4], v[5], v[6], v[7]);
            if (MODE == 1) {
                float dn = g_dinv[row0 + row];
                uint4 ps;
                ps.x = pack2h(v[0] * dn, v[1] * dn); ps.y = pack2h(v[2] * dn, v[3] * dn);
                ps.z = pack2h(v[4] * dn, v[5] * dn); ps.w = pack2h(v[6] * dn, v[7] * dn);
                *(uint4*)(Cs + base) = ps;
            }
        }
    } else {
        int r = tid >> 1, c2 = tid & 1;
        float s = 0.f;
#pragma unroll
        for (int c = 0; c < 64; c++)
            s = fmaf(fmaxf(sC[r * LDF + c] + sbias[c], 0.f), swm2[c * 2 + c2], s);
        if (row0 + r < NNODES)
            out[(size_t)(row0 + r) * 2 + c2] = s + __ldg(&bm2[c2]);
    }
}

// ---------------- propagation (fp16 gather, fp32 diagonal) ----------------
template <bool OUT_SCALED>
__global__ void __launch_bounds__(256) k_prop(
    const float* __restrict__ fin, const __half* __restrict__ fins,
    float* __restrict__ fout, __half* __restrict__ fouts)
{
    int n = (blockIdx.x * blockDim.x + threadIdx.x) >> 5;
    int lane = threadIdx.x & 31;
    int start = g_rowptr[n];
    int end = g_rowptr[n + 1];

    float ax = 0.f, ay = 0.f;
    for (int i = start; i < end; i += 32) {
        int cnt = min(32, end - i);
        int s = 0;
        if (lane < cnt) s = g_csrc[i + lane];
        int j = 0;
        for (; j + 4 <= cnt; j += 4) {
            int s0 = __shfl_sync(0xffffffffu, s, j);
            int s1 = __shfl_sync(0xffffffffu, s, j + 1);
            int s2 = __shfl_sync(0xffffffffu, s, j + 2);
            int s3 = __shfl_sync(0xffffffffu, s, j + 3);
            float2 v0 = __half22float2(*(const __half2*)&fins[(size_t)s0 * 64 + lane * 2]);
            float2 v1 = __half22float2(*(const __half2*)&fins[(size_t)s1 * 64 + lane * 2]);
            float2 v2 = __half22float2(*(const __half2*)&fins[(size_t)s2 * 64 + lane * 2]);
            float2 v3 = __half22float2(*(const __half2*)&fins[(size_t)s3 * 64 + lane * 2]);
            ax += (v0.x + v1.x) + (v2.x + v3.x);
            ay += (v0.y + v1.y) + (v2.y + v3.y);
        }
        for (; j < cnt; j++) {
            int sj = __shfl_sync(0xffffffffu, s, j);
            float2 v = __half22float2(*(const __half2*)&fins[(size_t)sj * 64 + lane * 2]);
            ax += v.x;
            ay += v.y;
        }
    }
    float dn = g_dinv[n];
    size_t base = (size_t)n * 64 + lane * 2;
    float2 cur = *(const float2*)&fin[base];
    float ox = cur.x - ax * dn;
    float oy = cur.y - ay * dn;
    *(float2*)&fout[base] = make_float2(ox, oy);
    if (OUT_SCALED)
        *(uint32_t*)&fouts[base] = pack2h(ox * dn, oy * dn);
}

// ---------------- launch ----------------
extern "C" void kernel_launch(void* const* d_in, const int* in_sizes, int n_in,
                              void* d_out, int out_size)
{
    const float* x   = (const float*)d_in[0];
    const void*  ei  = d_in[1];
    const float* W1  = (const float*)d_in[2];
    const float* b1  = (const float*)d_in[3];
    const float* W2  = (const float*)d_in[4];
    const float* b2  = (const float*)d_in[5];
    const float* Wm1 = (const float*)d_in[6];
    const float* bm1 = (const float*)d_in[7];
    const float* Wm2 = (const float*)d_in[8];
    const float* bm2 = (const float*)d_in[9];
    float* out = (float*)d_out;

    float *h1, *f0, *f1, *f2, *pwf;
    __half *f0s, *f1s;
    int *pdeg, *pflag;
    unsigned long long* pstate;
    cudaGetSymbolAddress((void**)&h1, g_h1);
    cudaGetSymbolAddress((void**)&f0, g_f0);
    cudaGetSymbolAddress((void**)&f1, g_f1);
    cudaGetSymbolAddress((void**)&f2, g_f2);
    cudaGetSymbolAddress((void**)&f0s, g_f0s);
    cudaGetSymbolAddress((void**)&f1s, g_f1s);
    cudaGetSymbolAddress((void**)&pwf, g_wfold);
    cudaGetSymbolAddress((void**)&pdeg, g_deg);
    cudaGetSymbolAddress((void**)&pflag, g_flag);
    cudaGetSymbolAddress((void**)&pstate, g_pstate);

    cudaFuncSetAttribute(k_mma<2, 0>, cudaFuncAttributeMaxDynamicSharedMemorySize, SMEM_SZ);
    cudaFuncSetAttribute(k_mma<1, 1>, cudaFuncAttributeMaxDynamicSharedMemorySize, SMEM_SZ);
    cudaFuncSetAttribute(k_mma<3, 2>, cudaFuncAttributeMaxDynamicSharedMemorySize, SMEM_SZ);

    // fork/join resources (handles only, no device memory)
    static cudaStream_t s_side = [] {
        cudaStream_t s;
        return (cudaStreamCreateWithFlags(&s, cudaStreamNonBlocking) == cudaSuccess)
                   ? s : (cudaStream_t)nullptr;
    }();
    static cudaEvent_t e_fork = [] {
        cudaEvent_t e;
        return (cudaEventCreateWithFlags(&e, cudaEventDisableTiming) == cudaSuccess)
                   ? e : (cudaEvent_t)nullptr;
    }();
    static cudaEvent_t e_dinv = [] {
        cudaEvent_t e;
        return (cudaEventCreateWithFlags(&e, cudaEventDisableTiming) == cudaSuccess)
                   ? e : (cudaEvent_t)nullptr;
    }();
    static cudaEvent_t e_join = [] {
        cudaEvent_t e;
        return (cudaEventCreateWithFlags(&e, cudaEventDisableTiming) == cudaSuccess)
                   ? e : (cudaEvent_t)nullptr;
    }();

    bool overlap = s_side && e_fork && e_dinv && e_join;
    cudaStream_t sp = overlap ? s_side : (cudaStream_t)0;

    if (overlap) {
        cudaEventRecord(e_fork, 0);
        cudaStreamWaitEvent(s_side, e_fork, 0);
    }

    // ---- prep chain (side stream) ----
    cudaMemsetAsync(pdeg, 0, NNODES * sizeof(int), sp);
    cudaMemsetAsync(pflag, 0, sizeof(int), sp);
    cudaMemsetAsync(pstate, 0, NBLK * sizeof(unsigned long long), sp);
    k_detect<<<1, 256, 0, sp>>>((const int*)ei);
    k_degree<<<NEDGES / 256, 256, 0, sp>>>(ei);
    k_scan_fused<<<NBLK, SCAN_B, 0, sp>>>();
    if (overlap) cudaEventRecord(e_dinv, s_side);     // dinv/rowptr ready
    k_fill<<<NEDGES / 256, 256, 0, sp>>>(ei);
    k_fold<<<(3 * 64 * 64 + 255) / 256, 256, 0, sp>>>(Wm1);
    if (overlap) cudaEventRecord(e_join, s_side);     // CSR + wfold ready

    // ---- MLP chain (main stream) ----
    k_mma<2, 0><<<NTILES, 256, SMEM_SZ>>>(x, x + 64, nullptr, 128, W1, b1,
                                          h1, nullptr, nullptr, nullptr, nullptr);
    if (overlap) cudaStreamWaitEvent(0, e_dinv, 0);   // GEMM2 prescale needs dinv
    k_mma<1, 1><<<NTILES, 256, SMEM_SZ>>>(h1, nullptr, nullptr, 64, W2, b2,
                                          f0, f0s, nullptr, nullptr, nullptr);
    if (overlap) cudaStreamWaitEvent(0, e_join, 0);   // props need CSR, head needs wfold

    // f1 = P f0, f2 = P f1
    k_prop<true><<<(NNODES * 32) / 256, 256>>>(f0, f0s, f1, f1s);
    k_prop<false><<<(NNODES * 32) / 256, 256>>>(f1, f1s, f2, nullptr);

    // head: out = relu(f0@Wf0 + f1@Wf1 + f2@Wf2 + bm1) @ Wm2 + bm2
    k_mma<3, 2><<<NTILES, 256, SMEM_SZ>>>(f0, f1, f2, 64, pwf, bm1,
                                          nullptr, nullptr, Wm2, bm2, out);
}